// round 5
// baseline (speedup 1.0000x reference)
#include <cuda_runtime.h>
#include <cuda_fp16.h>
#include <cstdint>

#define N_NODES   50000
#define N_EDGES_C 1600000
#define TILE_E    128
#define PC_TILE   64

// Scratch: per-node [vfeat@W1_recv + 0.5*b1 | vfeat@W1_send + 0.5*b1], 50000 x 256 f32
__device__ float g_P[(size_t)N_NODES * 256];

// ============================ helpers ============================
__device__ __forceinline__ void mma_f16(float* c, const uint32_t* a, uint32_t b0, uint32_t b1) {
    asm volatile("mma.sync.aligned.m16n8k16.row.col.f32.f16.f16.f32 "
        "{%0,%1,%2,%3}, {%4,%5,%6,%7}, {%8,%9}, {%0,%1,%2,%3};"
        : "+f"(c[0]), "+f"(c[1]), "+f"(c[2]), "+f"(c[3])
        : "r"(a[0]), "r"(a[1]), "r"(a[2]), "r"(a[3]), "r"(b0), "r"(b1));
}

__device__ __forceinline__ uint32_t pack_h2(float x, float y) {
    __half2 h = __floats2half2_rn(x, y);
    return *reinterpret_cast<uint32_t*>(&h);
}
// weight hi/lo split (w = hi + lo exact to ~2^-22)
__device__ __forceinline__ void wsplit(float w0, float w1, uint32_t& hi, uint32_t& lo) {
    float h0 = __half2float(__float2half_rn(w0));
    float h1 = __half2float(__float2half_rn(w1));
    hi = pack_h2(h0, h1);
    lo = pack_h2(w0 - h0, w1 - h1);
}

// ---------------------------------------------------------------------------
// Precompute P[n] = [vfeat[n]@W1_recv + 0.5 b1 | vfeat[n]@W1_send + 0.5 b1]
// ---------------------------------------------------------------------------
__global__ void __launch_bounds__(256)
precompute_kernel(const float* __restrict__ vfeat, const float* __restrict__ W1,
                  const float* __restrict__ b1) {
    extern __shared__ char smraw[];
    float* sW = (float*)smraw;               // [64][256]
    float* sV = (float*)smraw + 64 * 256;    // [64][64]
    const int tid = threadIdx.x;
    const int n0  = blockIdx.x * PC_TILE;

    for (int idx = tid; idx < 64 * 256; idx += 256) {
        int k = idx >> 8, j = idx & 255;
        sW[idx] = (j < 128) ? W1[(64 + k) * 128 + j]
                            : W1[(128 + k) * 128 + (j - 128)];
    }
    for (int idx = tid; idx < PC_TILE * 64; idx += 256) {
        int n = idx >> 6;
        sV[idx] = (n0 + n < N_NODES) ? vfeat[(size_t)(n0 + n) * 64 + (idx & 63)] : 0.0f;
    }
    __syncthreads();

    const int tx = tid & 31;
    const int ty = tid >> 5;
    float acc[8][8];
#pragma unroll
    for (int i = 0; i < 8; i++)
#pragma unroll
        for (int j = 0; j < 8; j++) acc[i][j] = 0.0f;

    const float* vb = sV + ty * 8 * 64;
    const float* wb = sW + tx * 8;
#pragma unroll 4
    for (int k = 0; k < 64; ++k) {
        float4 wa = *(const float4*)(wb + k * 256);
        float4 wc = *(const float4*)(wb + k * 256 + 4);
        float wv[8] = {wa.x, wa.y, wa.z, wa.w, wc.x, wc.y, wc.z, wc.w};
#pragma unroll
        for (int i = 0; i < 8; i++) {
            float v = vb[i * 64 + k];
#pragma unroll
            for (int j = 0; j < 8; j++) acc[i][j] += v * wv[j];
        }
    }
    // fold 0.5*b1 into both halves
    float bh[8];
#pragma unroll
    for (int j = 0; j < 8; j++) bh[j] = 0.5f * b1[(tx * 8 + j) & 127];

#pragma unroll
    for (int i = 0; i < 8; i++) {
        int node = n0 + ty * 8 + i;
        if (node < N_NODES) {
            float* dst = g_P + (size_t)node * 256 + tx * 8;
            *(float4*)(dst)     = make_float4(acc[i][0] + bh[0], acc[i][1] + bh[1],
                                              acc[i][2] + bh[2], acc[i][3] + bh[3]);
            *(float4*)(dst + 4) = make_float4(acc[i][4] + bh[4], acc[i][5] + bh[5],
                                              acc[i][6] + bh[6], acc[i][7] + bh[7]);
        }
    }
}

// ---------------------------------------------------------------------------
// Persistent HMMA edge kernel. 8 warps/CTA, each warp owns 16 rows of a
// 128-edge tile, fully register-resident, fp16 2-term (W split hi/lo):
//   acc1 <- gather(P_recv + P_send)        (b1 pre-folded)
//   acc1 += Xh@W1hi + Xh@W1lo
//   A2   <- relu(acc1) -> fp16
//   acc2 <- b2 ; acc2 += A2@W2hi + A2@W2lo
// No __syncthreads in the main loop.
// ---------------------------------------------------------------------------
__global__ void __launch_bounds__(256, 1)
edge_kernel(const float* __restrict__ edata,
            const float* __restrict__ W1,
            const float* __restrict__ W2,
            const float* __restrict__ b2,
            const void*  __restrict__ senders,
            const void*  __restrict__ receivers,
            float* __restrict__ out) {
    extern __shared__ char smraw[];
    uint4* w1f = (uint4*)smraw;              // [16 j][4 s][32 lane] {b0h,b1h,b0l,b1l}
    uint4* w2f = w1f + 2048;                 // [8 j][8 t][32 lane]
    float* b2f = (float*)(w2f + 2048);       // 64
    int*   sFlag = (int*)(b2f + 64);

    const int tid = threadIdx.x;
    const int wid = tid >> 5, lid = tid & 31;
    const int gq  = lid >> 2;     // fragment row
    const int tg  = lid & 3;      // fragment col pair

    // ---- index dtype detection (int64 -> high words of first 32 elems zero)
    if (tid < 32) {
        unsigned hiw = ((const unsigned*)senders)[2 * tid + 1];
        unsigned ball = __ballot_sync(0xffffffffu, hiw == 0u);
        if (tid == 0) *sFlag = (ball == 0xffffffffu);
    }

    // ---- Stage W1 fragments, fragment-ordered, fp16 hi/lo interleaved
    for (int idx = tid; idx < 2048; idx += 256) {
        int lane = idx & 31, s = (idx >> 5) & 3, j = idx >> 7;
        int k = 16 * s + 2 * (lane & 3);
        int n = 8 * j + (lane >> 2);
        uint4 f;
        wsplit(W1[k * 128 + n],       W1[(k + 1) * 128 + n], f.x, f.z);
        wsplit(W1[(k + 8) * 128 + n], W1[(k + 9) * 128 + n], f.y, f.w);
        w1f[idx] = f;
    }
    // ---- Stage W2 fragments
    for (int idx = tid; idx < 2048; idx += 256) {
        int lane = idx & 31, t = (idx >> 5) & 7, j = idx >> 8;
        int k = 16 * t + 2 * (lane & 3);
        int n = 8 * j + (lane >> 2);
        uint4 f;
        wsplit(W2[k * 64 + n],       W2[(k + 1) * 64 + n], f.x, f.z);
        wsplit(W2[(k + 8) * 64 + n], W2[(k + 9) * 64 + n], f.y, f.w);
        w2f[idx] = f;
    }
    if (tid < 64) b2f[tid] = b2[tid];
    __syncthreads();

    const int idx64 = *sFlag;
    const long long* r64 = (const long long*)receivers;
    const int*       r32 = (const int*)receivers;
    const long long* s64 = (const long long*)senders;
    const int*       s32 = (const int*)senders;

    const int ntiles = N_EDGES_C / TILE_E;

    for (int tile = blockIdx.x; tile < ntiles; tile += gridDim.x) {
        const int e0  = tile * TILE_E;
        const int em0 = e0 + wid * 16 + gq;   // first edge row of this lane
        const int em1 = em0 + 8;              // second edge row

        const int r0 = idx64 ? (int)r64[em0] : r32[em0];
        const int s0 = idx64 ? (int)s64[em0] : s32[em0];
        const int r1 = idx64 ? (int)r64[em1] : r32[em1];
        const int s1 = idx64 ? (int)s64[em1] : s32[em1];

        const float* pr0 = g_P + (size_t)r0 * 256;
        const float* ps0 = g_P + (size_t)s0 * 256 + 128;
        const float* pr1 = g_P + (size_t)r1 * 256;
        const float* ps1 = g_P + (size_t)s1 * 256 + 128;

        // ---- acc1 init: gather P_recv + P_send (b1 pre-folded), C-frag layout
        float c1[16][4];
#pragma unroll
        for (int j = 0; j < 16; j++) {
            int col = 8 * j + 2 * tg;
            float2 a = *(const float2*)(pr0 + col);
            float2 b = *(const float2*)(ps0 + col);
            float2 c = *(const float2*)(pr1 + col);
            float2 d = *(const float2*)(ps1 + col);
            c1[j][0] = a.x + b.x;
            c1[j][1] = a.y + b.y;
            c1[j][2] = c.x + d.x;
            c1[j][3] = c.y + d.y;
        }

        // ---- A1 fragments from edata (fp16 quantize)
        uint32_t a1[4][4];
        const float* x0 = edata + (size_t)em0 * 64;
        const float* x1 = edata + (size_t)em1 * 64;
#pragma unroll
        for (int s = 0; s < 4; s++) {
            int k = 16 * s + 2 * tg;
            float2 v0 = *(const float2*)(x0 + k);
            float2 v1 = *(const float2*)(x1 + k);
            float2 v2 = *(const float2*)(x0 + k + 8);
            float2 v3 = *(const float2*)(x1 + k + 8);
            a1[s][0] = pack_h2(v0.x, v0.y);
            a1[s][1] = pack_h2(v1.x, v1.y);
            a1[s][2] = pack_h2(v2.x, v2.y);
            a1[s][3] = pack_h2(v3.x, v3.y);
        }

        // ---- GEMM1: c1 += X@W1hi + X@W1lo
#pragma unroll
        for (int j = 0; j < 16; j++) {
#pragma unroll
            for (int s = 0; s < 4; s++) {
                uint4 f = w1f[(j * 4 + s) * 32 + lid];
                mma_f16(c1[j], a1[s], f.x, f.y);
                mma_f16(c1[j], a1[s], f.z, f.w);
            }
        }

        // ---- relu + fp16 quantize: C-frag -> A-frag (register-local)
        uint32_t a2[8][4];
#pragma unroll
        for (int t = 0; t < 8; t++) {
            a2[t][0] = pack_h2(fmaxf(c1[2 * t][0], 0.0f),     fmaxf(c1[2 * t][1], 0.0f));
            a2[t][1] = pack_h2(fmaxf(c1[2 * t][2], 0.0f),     fmaxf(c1[2 * t][3], 0.0f));
            a2[t][2] = pack_h2(fmaxf(c1[2 * t + 1][0], 0.0f), fmaxf(c1[2 * t + 1][1], 0.0f));
            a2[t][3] = pack_h2(fmaxf(c1[2 * t + 1][2], 0.0f), fmaxf(c1[2 * t + 1][3], 0.0f));
        }

        // ---- acc2 init from b2
        float d2[8][4];
#pragma unroll
        for (int j = 0; j < 8; j++) {
            float2 bb = *(const float2*)(b2f + 8 * j + 2 * tg);
            d2[j][0] = bb.x; d2[j][1] = bb.y; d2[j][2] = bb.x; d2[j][3] = bb.y;
        }

        // ---- GEMM2: d2 += H@W2hi + H@W2lo
#pragma unroll
        for (int j = 0; j < 8; j++) {
#pragma unroll
            for (int t = 0; t < 8; t++) {
                uint4 f = w2f[(j * 8 + t) * 32 + lid];
                mma_f16(d2[j], a2[t], f.x, f.y);
                mma_f16(d2[j], a2[t], f.z, f.w);
            }
        }

        // ---- store
        float* o0 = out + (size_t)em0 * 64;
        float* o1 = out + (size_t)em1 * 64;
#pragma unroll
        for (int j = 0; j < 8; j++) {
            int col = 8 * j + 2 * tg;
            *(float2*)(o0 + col) = make_float2(d2[j][0], d2[j][1]);
            *(float2*)(o1 + col) = make_float2(d2[j][2], d2[j][3]);
        }
    }
}

// ---------------------------------------------------------------------------
extern "C" void kernel_launch(void* const* d_in, const int* in_sizes, int n_in,
                              void* d_out, int out_size) {
    const float* edata     = (const float*)d_in[0];
    const float* vfeat     = (const float*)d_in[1];
    const float* W1        = (const float*)d_in[2];
    const float* b1        = (const float*)d_in[3];
    const float* W2        = (const float*)d_in[4];
    const float* b2        = (const float*)d_in[5];
    const void*  senders   = d_in[6];
    const void*  receivers = d_in[7];
    float* out = (float*)d_out;
    (void)in_sizes; (void)n_in; (void)out_size;

    const int pc_smem = (64 * 256 + PC_TILE * 64) * 4;             // 81920 B
    const int e_smem  = 2 * 2048 * 16 + 64 * 4 + 16;               // 65808 B

    cudaFuncSetAttribute(precompute_kernel,
                         cudaFuncAttributeMaxDynamicSharedMemorySize, pc_smem);
    cudaFuncSetAttribute(edge_kernel,
                         cudaFuncAttributeMaxDynamicSharedMemorySize, e_smem);

    int sms = 0;
    cudaDeviceGetAttribute(&sms, cudaDevAttrMultiProcessorCount, 0);
    if (sms <= 0) sms = 148;

    precompute_kernel<<<(N_NODES + PC_TILE - 1) / PC_TILE, 256, pc_smem>>>(vfeat, W1, b1);
    edge_kernel<<<sms, 256, e_smem>>>(edata, W1, W2, b2, senders, receivers, out);
}

// round 6
// speedup vs baseline: 1.4262x; 1.4262x over previous
#include <cuda_runtime.h>
#include <cuda_bf16.h>
#include <cstdint>

#define N_NODES   50000
#define N_EDGES_C 1600000
#define TILE_E    256
#define PC_TILE   64

// Scratch: per-node [vfeat@W1_recv + 0.5*b1 | vfeat@W1_send + 0.5*b1], 50000 x 256 f32
__device__ float g_P[(size_t)N_NODES * 256];

// ============================ helpers ============================
__device__ __forceinline__ void mma_bf16(float* c, const uint32_t* a, uint32_t b0, uint32_t b1) {
    asm volatile("mma.sync.aligned.m16n8k16.row.col.f32.bf16.bf16.f32 "
        "{%0,%1,%2,%3}, {%4,%5,%6,%7}, {%8,%9}, {%0,%1,%2,%3};"
        : "+f"(c[0]), "+f"(c[1]), "+f"(c[2]), "+f"(c[3])
        : "r"(a[0]), "r"(a[1]), "r"(a[2]), "r"(a[3]), "r"(b0), "r"(b1));
}

__device__ __forceinline__ void split2(float x, float y, uint32_t& hi, uint32_t& lo) {
    __nv_bfloat16 xh = __float2bfloat16(x);
    __nv_bfloat16 yh = __float2bfloat16(y);
    __nv_bfloat16 xl = __float2bfloat16(x - __bfloat162float(xh));
    __nv_bfloat16 yl = __float2bfloat16(y - __bfloat162float(yh));
    __nv_bfloat162 h; h.x = xh; h.y = yh;
    __nv_bfloat162 l; l.x = xl; l.y = yl;
    hi = *reinterpret_cast<uint32_t*>(&h);
    lo = *reinterpret_cast<uint32_t*>(&l);
}

// ---------------------------------------------------------------------------
// Precompute P[n] = [vfeat[n]@W1_recv + 0.5 b1 | vfeat[n]@W1_send + 0.5 b1]
// ---------------------------------------------------------------------------
__global__ void __launch_bounds__(256)
precompute_kernel(const float* __restrict__ vfeat, const float* __restrict__ W1,
                  const float* __restrict__ b1) {
    extern __shared__ char smraw[];
    float* sW = (float*)smraw;               // [64][256]
    float* sV = (float*)smraw + 64 * 256;    // [64][64]
    const int tid = threadIdx.x;
    const int n0  = blockIdx.x * PC_TILE;

    for (int idx = tid; idx < 64 * 256; idx += 256) {
        int k = idx >> 8, j = idx & 255;
        sW[idx] = (j < 128) ? W1[(64 + k) * 128 + j]
                            : W1[(128 + k) * 128 + (j - 128)];
    }
    for (int idx = tid; idx < PC_TILE * 64; idx += 256) {
        int n = idx >> 6;
        sV[idx] = (n0 + n < N_NODES) ? vfeat[(size_t)(n0 + n) * 64 + (idx & 63)] : 0.0f;
    }
    __syncthreads();

    const int tx = tid & 31;
    const int ty = tid >> 5;
    float acc[8][8];
#pragma unroll
    for (int i = 0; i < 8; i++)
#pragma unroll
        for (int j = 0; j < 8; j++) acc[i][j] = 0.0f;

    const float* vb = sV + ty * 8 * 64;
    const float* wb = sW + tx * 8;
#pragma unroll 4
    for (int k = 0; k < 64; ++k) {
        float4 wa = *(const float4*)(wb + k * 256);
        float4 wc = *(const float4*)(wb + k * 256 + 4);
        float wv[8] = {wa.x, wa.y, wa.z, wa.w, wc.x, wc.y, wc.z, wc.w};
#pragma unroll
        for (int i = 0; i < 8; i++) {
            float v = vb[i * 64 + k];
#pragma unroll
            for (int j = 0; j < 8; j++) acc[i][j] += v * wv[j];
        }
    }
    float bh[8];
#pragma unroll
    for (int j = 0; j < 8; j++) bh[j] = 0.5f * b1[(tx * 8 + j) & 127];

#pragma unroll
    for (int i = 0; i < 8; i++) {
        int node = n0 + ty * 8 + i;
        if (node < N_NODES) {
            float* dst = g_P + (size_t)node * 256 + tx * 8;
            *(float4*)(dst)     = make_float4(acc[i][0] + bh[0], acc[i][1] + bh[1],
                                              acc[i][2] + bh[2], acc[i][3] + bh[3]);
            *(float4*)(dst + 4) = make_float4(acc[i][4] + bh[4], acc[i][5] + bh[5],
                                              acc[i][6] + bh[6], acc[i][7] + bh[7]);
        }
    }
}

// ---------------------------------------------------------------------------
// Persistent HMMA edge kernel, bf16 3-term, M=32 rows/warp (2 m16 blocks).
// Each B-fragment uint4 {b0h,b1h,b0l,b1l} (one LDS.128) feeds 6 mmas.
// No __syncthreads in the main loop.
// ---------------------------------------------------------------------------
__global__ void __launch_bounds__(256, 1)
edge_kernel(const float* __restrict__ edata,
            const float* __restrict__ W1,
            const float* __restrict__ W2,
            const float* __restrict__ b2,
            const void*  __restrict__ senders,
            const void*  __restrict__ receivers,
            float* __restrict__ out) {
    extern __shared__ char smraw[];
    uint4* w1f = (uint4*)smraw;              // [16 j][4 s][32 lane] {b0h,b1h,b0l,b1l}
    uint4* w2f = w1f + 2048;                 // [8 j][8 t][32 lane]
    float* b2f = (float*)(w2f + 2048);       // 64
    int*   sFlag = (int*)(b2f + 64);

    const int tid = threadIdx.x;
    const int wid = tid >> 5, lid = tid & 31;
    const int gq  = lid >> 2;     // fragment row
    const int tg  = lid & 3;      // fragment col pair

    // ---- index dtype detection (int64 -> high words of first 32 elems zero)
    if (tid < 32) {
        unsigned hiw = ((const unsigned*)senders)[2 * tid + 1];
        unsigned ball = __ballot_sync(0xffffffffu, hiw == 0u);
        if (tid == 0) *sFlag = (ball == 0xffffffffu);
    }

    // ---- Stage W1 fragments, fragment-ordered, bf16 hi/lo interleaved
    for (int idx = tid; idx < 2048; idx += 256) {
        int lane = idx & 31, s = (idx >> 5) & 3, j = idx >> 7;
        int k = 16 * s + 2 * (lane & 3);
        int n = 8 * j + (lane >> 2);
        uint4 f;
        split2(W1[k * 128 + n],       W1[(k + 1) * 128 + n], f.x, f.z);
        split2(W1[(k + 8) * 128 + n], W1[(k + 9) * 128 + n], f.y, f.w);
        w1f[idx] = f;
    }
    // ---- Stage W2 fragments
    for (int idx = tid; idx < 2048; idx += 256) {
        int lane = idx & 31, t = (idx >> 5) & 7, j = idx >> 8;
        int k = 16 * t + 2 * (lane & 3);
        int n = 8 * j + (lane >> 2);
        uint4 f;
        split2(W2[k * 64 + n],       W2[(k + 1) * 64 + n], f.x, f.z);
        split2(W2[(k + 8) * 64 + n], W2[(k + 9) * 64 + n], f.y, f.w);
        w2f[idx] = f;
    }
    if (tid < 64) b2f[tid] = b2[tid];
    __syncthreads();

    const int idx64 = *sFlag;
    const long long* r64 = (const long long*)receivers;
    const int*       r32 = (const int*)receivers;
    const long long* s64 = (const long long*)senders;
    const int*       s32 = (const int*)senders;

    const int ntiles = N_EDGES_C / TILE_E;

    for (int tile = blockIdx.x; tile < ntiles; tile += gridDim.x) {
        const int base = tile * TILE_E + wid * 32 + gq;
        // 4 row streams: block b rows base+16b, base+16b+8
        int em[4];
        em[0] = base;      em[1] = base + 8;
        em[2] = base + 16; em[3] = base + 24;

        const float* pr[4];
        const float* ps[4];
#pragma unroll
        for (int q = 0; q < 4; q++) {
            int rr = idx64 ? (int)r64[em[q]] : r32[em[q]];
            int ss = idx64 ? (int)s64[em[q]] : s32[em[q]];
            pr[q] = g_P + (size_t)rr * 256;
            ps[q] = g_P + (size_t)ss * 256 + 128;
        }

        // ---- acc init: gather P_recv + P_send (b1 pre-folded), C-frag layout
        float c1[2][16][4];
#pragma unroll
        for (int j = 0; j < 16; j++) {
            int col = 8 * j + 2 * tg;
#pragma unroll
            for (int b = 0; b < 2; b++) {
                float2 a0 = *(const float2*)(pr[2 * b] + col);
                float2 b0 = *(const float2*)(ps[2 * b] + col);
                float2 a1 = *(const float2*)(pr[2 * b + 1] + col);
                float2 b1v = *(const float2*)(ps[2 * b + 1] + col);
                c1[b][j][0] = a0.x + b0.x;
                c1[b][j][1] = a0.y + b0.y;
                c1[b][j][2] = a1.x + b1v.x;
                c1[b][j][3] = a1.y + b1v.y;
            }
        }

        // ---- A1 fragments from edata (bf16 hi/lo split)
        uint32_t ah[2][4][4], al[2][4][4];
#pragma unroll
        for (int b = 0; b < 2; b++) {
            const float* x0 = edata + (size_t)em[2 * b] * 64;
            const float* x1 = edata + (size_t)em[2 * b + 1] * 64;
#pragma unroll
            for (int s = 0; s < 4; s++) {
                int k = 16 * s + 2 * tg;
                float2 v0 = *(const float2*)(x0 + k);
                float2 v1 = *(const float2*)(x1 + k);
                float2 v2 = *(const float2*)(x0 + k + 8);
                float2 v3 = *(const float2*)(x1 + k + 8);
                split2(v0.x, v0.y, ah[b][s][0], al[b][s][0]);
                split2(v1.x, v1.y, ah[b][s][1], al[b][s][1]);
                split2(v2.x, v2.y, ah[b][s][2], al[b][s][2]);
                split2(v3.x, v3.y, ah[b][s][3], al[b][s][3]);
            }
        }

        // ---- GEMM1: c1 += Xh@W1h + Xl@W1h + Xh@W1l  (each uint4 feeds 6 mmas)
#pragma unroll
        for (int j = 0; j < 16; j++) {
#pragma unroll
            for (int s = 0; s < 4; s++) {
                uint4 f = w1f[(j * 4 + s) * 32 + lid];
#pragma unroll
                for (int b = 0; b < 2; b++) {
                    mma_bf16(c1[b][j], ah[b][s], f.x, f.y);
                    mma_bf16(c1[b][j], al[b][s], f.x, f.y);
                    mma_bf16(c1[b][j], ah[b][s], f.z, f.w);
                }
            }
        }

        // ---- relu + bf16 split: C-frag -> A-frag (register-local)
        uint32_t a2h[2][8][4], a2l[2][8][4];
#pragma unroll
        for (int b = 0; b < 2; b++) {
#pragma unroll
            for (int t = 0; t < 8; t++) {
                split2(fmaxf(c1[b][2 * t][0], 0.0f),     fmaxf(c1[b][2 * t][1], 0.0f),
                       a2h[b][t][0], a2l[b][t][0]);
                split2(fmaxf(c1[b][2 * t][2], 0.0f),     fmaxf(c1[b][2 * t][3], 0.0f),
                       a2h[b][t][1], a2l[b][t][1]);
                split2(fmaxf(c1[b][2 * t + 1][0], 0.0f), fmaxf(c1[b][2 * t + 1][1], 0.0f),
                       a2h[b][t][2], a2l[b][t][2]);
                split2(fmaxf(c1[b][2 * t + 1][2], 0.0f), fmaxf(c1[b][2 * t + 1][3], 0.0f),
                       a2h[b][t][3], a2l[b][t][3]);
            }
        }

        // ---- acc2 init from b2
        float d2[2][8][4];
#pragma unroll
        for (int j = 0; j < 8; j++) {
            float2 bb = *(const float2*)(b2f + 8 * j + 2 * tg);
#pragma unroll
            for (int b = 0; b < 2; b++) {
                d2[b][j][0] = bb.x; d2[b][j][1] = bb.y;
                d2[b][j][2] = bb.x; d2[b][j][3] = bb.y;
            }
        }

        // ---- GEMM2: d2 += Hh@W2h + Hl@W2h + Hh@W2l
#pragma unroll
        for (int j = 0; j < 8; j++) {
#pragma unroll
            for (int t = 0; t < 8; t++) {
                uint4 f = w2f[(j * 8 + t) * 32 + lid];
#pragma unroll
                for (int b = 0; b < 2; b++) {
                    mma_bf16(d2[b][j], a2h[b][t], f.x, f.y);
                    mma_bf16(d2[b][j], a2l[b][t], f.x, f.y);
                    mma_bf16(d2[b][j], a2h[b][t], f.z, f.w);
                }
            }
        }

        // ---- store
#pragma unroll
        for (int b = 0; b < 2; b++) {
            float* o0 = out + (size_t)em[2 * b] * 64;
            float* o1 = out + (size_t)em[2 * b + 1] * 64;
#pragma unroll
            for (int j = 0; j < 8; j++) {
                int col = 8 * j + 2 * tg;
                *(float2*)(o0 + col) = make_float2(d2[b][j][0], d2[b][j][1]);
                *(float2*)(o1 + col) = make_float2(d2[b][j][2], d2[b][j][3]);
            }
        }
    }
}

// ---------------------------------------------------------------------------
extern "C" void kernel_launch(void* const* d_in, const int* in_sizes, int n_in,
                              void* d_out, int out_size) {
    const float* edata     = (const float*)d_in[0];
    const float* vfeat     = (const float*)d_in[1];
    const float* W1        = (const float*)d_in[2];
    const float* b1        = (const float*)d_in[3];
    const float* W2        = (const float*)d_in[4];
    const float* b2        = (const float*)d_in[5];
    const void*  senders   = d_in[6];
    const void*  receivers = d_in[7];
    float* out = (float*)d_out;
    (void)in_sizes; (void)n_in; (void)out_size;

    const int pc_smem = (64 * 256 + PC_TILE * 64) * 4;             // 81920 B
    const int e_smem  = 2 * 2048 * 16 + 64 * 4 + 16;               // 65808 B

    cudaFuncSetAttribute(precompute_kernel,
                         cudaFuncAttributeMaxDynamicSharedMemorySize, pc_smem);
    cudaFuncSetAttribute(edge_kernel,
                         cudaFuncAttributeMaxDynamicSharedMemorySize, e_smem);

    int sms = 0;
    cudaDeviceGetAttribute(&sms, cudaDevAttrMultiProcessorCount, 0);
    if (sms <= 0) sms = 148;

    precompute_kernel<<<(N_NODES + PC_TILE - 1) / PC_TILE, 256, pc_smem>>>(vfeat, W1, b1);
    edge_kernel<<<sms, 256, e_smem>>>(edata, W1, W2, b2, senders, receivers, out);
}

// round 7
// speedup vs baseline: 1.6272x; 1.1409x over previous
#include <cuda_runtime.h>
#include <cuda_bf16.h>
#include <cuda_fp16.h>
#include <cstdint>

#define N_NODES   50000
#define N_EDGES_C 1600000
#define TILE_E    256
#define PC_TILE   64

// Scratch: per-node fp16 [vfeat@W1_recv + 0.5*b1 | vfeat@W1_send + 0.5*b1],
// permuted fragment-major: half index = h*128 + tg*32 + j*2 + c
// (h: 0=recv,1=send; tg=(col>>1)&3; j=col>>3; c=col&1), 50000 x 256 fp16 (25.6 MB)
__device__ __half g_Ph[(size_t)N_NODES * 256];

// ============================ helpers ============================
__device__ __forceinline__ void mma_bf16(float* c, const uint32_t* a, uint32_t b0, uint32_t b1) {
    asm volatile("mma.sync.aligned.m16n8k16.row.col.f32.bf16.bf16.f32 "
        "{%0,%1,%2,%3}, {%4,%5,%6,%7}, {%8,%9}, {%0,%1,%2,%3};"
        : "+f"(c[0]), "+f"(c[1]), "+f"(c[2]), "+f"(c[3])
        : "r"(a[0]), "r"(a[1]), "r"(a[2]), "r"(a[3]), "r"(b0), "r"(b1));
}

__device__ __forceinline__ void split2(float x, float y, uint32_t& hi, uint32_t& lo) {
    __nv_bfloat16 xh = __float2bfloat16(x);
    __nv_bfloat16 yh = __float2bfloat16(y);
    __nv_bfloat16 xl = __float2bfloat16(x - __bfloat162float(xh));
    __nv_bfloat16 yl = __float2bfloat16(y - __bfloat162float(yh));
    __nv_bfloat162 h; h.x = xh; h.y = yh;
    __nv_bfloat162 l; l.x = xl; l.y = yl;
    hi = *reinterpret_cast<uint32_t*>(&h);
    lo = *reinterpret_cast<uint32_t*>(&l);
}

__device__ __forceinline__ float2 h2f(uint32_t u) {
    __half2 h = *reinterpret_cast<__half2*>(&u);
    return __half22float2(h);
}

// ---------------------------------------------------------------------------
// Precompute P[n] = [vfeat[n]@W1_recv + 0.5 b1 | vfeat[n]@W1_send + 0.5 b1],
// stored fp16 in fragment-permuted order.
// ---------------------------------------------------------------------------
__global__ void __launch_bounds__(256)
precompute_kernel(const float* __restrict__ vfeat, const float* __restrict__ W1,
                  const float* __restrict__ b1) {
    extern __shared__ char smraw[];
    float* sW = (float*)smraw;               // [64][256]
    float* sV = (float*)smraw + 64 * 256;    // [64][64]
    const int tid = threadIdx.x;
    const int n0  = blockIdx.x * PC_TILE;

    for (int idx = tid; idx < 64 * 256; idx += 256) {
        int k = idx >> 8, j = idx & 255;
        sW[idx] = (j < 128) ? W1[(64 + k) * 128 + j]
                            : W1[(128 + k) * 128 + (j - 128)];
    }
    for (int idx = tid; idx < PC_TILE * 64; idx += 256) {
        int n = idx >> 6;
        sV[idx] = (n0 + n < N_NODES) ? vfeat[(size_t)(n0 + n) * 64 + (idx & 63)] : 0.0f;
    }
    __syncthreads();

    const int tx = tid & 31;
    const int ty = tid >> 5;
    float acc[8][8];
#pragma unroll
    for (int i = 0; i < 8; i++)
#pragma unroll
        for (int j = 0; j < 8; j++) acc[i][j] = 0.0f;

    const float* vb = sV + ty * 8 * 64;
    const float* wb = sW + tx * 8;
#pragma unroll 4
    for (int k = 0; k < 64; ++k) {
        float4 wa = *(const float4*)(wb + k * 256);
        float4 wc = *(const float4*)(wb + k * 256 + 4);
        float wv[8] = {wa.x, wa.y, wa.z, wa.w, wc.x, wc.y, wc.z, wc.w};
#pragma unroll
        for (int i = 0; i < 8; i++) {
            float v = vb[i * 64 + k];
#pragma unroll
            for (int j = 0; j < 8; j++) acc[i][j] += v * wv[j];
        }
    }
    float bh[8];
#pragma unroll
    for (int j = 0; j < 8; j++) bh[j] = 0.5f * b1[(tx * 8 + j) & 127];

#pragma unroll
    for (int i = 0; i < 8; i++) {
        int node = n0 + ty * 8 + i;
        if (node < N_NODES) {
            __half* dst = g_Ph + (size_t)node * 256;
#pragma unroll
            for (int j = 0; j < 8; j++) {
                int C = tx * 8 + j;                 // global output col 0..255
                int h = C >> 7, c = C & 127;
                int jj = c >> 3, tg = (c >> 1) & 3, cc = c & 1;
                dst[h * 128 + tg * 32 + jj * 2 + cc] = __float2half(acc[i][j] + bh[j]);
            }
        }
    }
}

// ---------------------------------------------------------------------------
// Persistent HMMA edge kernel, bf16 3-term, M=32 rows/warp.
// fp16 permuted P gather: 4x LDG.128 per row-half, fully dense wavefronts.
// ---------------------------------------------------------------------------
__global__ void __launch_bounds__(256, 1)
edge_kernel(const float* __restrict__ edata,
            const float* __restrict__ W1,
            const float* __restrict__ W2,
            const float* __restrict__ b2,
            const void*  __restrict__ senders,
            const void*  __restrict__ receivers,
            float* __restrict__ out) {
    extern __shared__ char smraw[];
    uint4* w1f = (uint4*)smraw;              // [16 j][4 s][32 lane] {b0h,b1h,b0l,b1l}
    uint4* w2f = w1f + 2048;                 // [8 j][8 t][32 lane]
    float* b2f = (float*)(w2f + 2048);       // 64
    int*   sFlag = (int*)(b2f + 64);

    const int tid = threadIdx.x;
    const int wid = tid >> 5, lid = tid & 31;
    const int gq  = lid >> 2;     // fragment row
    const int tg  = lid & 3;      // fragment col pair

    if (tid < 32) {
        unsigned hiw = ((const unsigned*)senders)[2 * tid + 1];
        unsigned ball = __ballot_sync(0xffffffffu, hiw == 0u);
        if (tid == 0) *sFlag = (ball == 0xffffffffu);
    }

    // ---- Stage W1 fragments, fragment-ordered, bf16 hi/lo interleaved
    for (int idx = tid; idx < 2048; idx += 256) {
        int lane = idx & 31, s = (idx >> 5) & 3, j = idx >> 7;
        int k = 16 * s + 2 * (lane & 3);
        int n = 8 * j + (lane >> 2);
        uint4 f;
        split2(W1[k * 128 + n],       W1[(k + 1) * 128 + n], f.x, f.z);
        split2(W1[(k + 8) * 128 + n], W1[(k + 9) * 128 + n], f.y, f.w);
        w1f[idx] = f;
    }
    for (int idx = tid; idx < 2048; idx += 256) {
        int lane = idx & 31, t = (idx >> 5) & 7, j = idx >> 8;
        int k = 16 * t + 2 * (lane & 3);
        int n = 8 * j + (lane >> 2);
        uint4 f;
        split2(W2[k * 64 + n],       W2[(k + 1) * 64 + n], f.x, f.z);
        split2(W2[(k + 8) * 64 + n], W2[(k + 9) * 64 + n], f.y, f.w);
        w2f[idx] = f;
    }
    if (tid < 64) b2f[tid] = b2[tid];
    __syncthreads();

    const int idx64 = *sFlag;
    const long long* r64 = (const long long*)receivers;
    const int*       r32 = (const int*)receivers;
    const long long* s64 = (const long long*)senders;
    const int*       s32 = (const int*)senders;

    const char* Pbase = (const char*)g_Ph;
    const int ntiles = N_EDGES_C / TILE_E;

    for (int tile = blockIdx.x; tile < ntiles; tile += gridDim.x) {
        const int base = tile * TILE_E + wid * 32 + gq;
        int em[4];
        em[0] = base;      em[1] = base + 8;
        em[2] = base + 16; em[3] = base + 24;

        const char* pr[4];   // recv row-half base (permuted fp16, +tg*64)
        const char* ps[4];   // send row-half base
#pragma unroll
        for (int q = 0; q < 4; q++) {
            int rr = idx64 ? (int)r64[em[q]] : r32[em[q]];
            int ss = idx64 ? (int)s64[em[q]] : s32[em[q]];
            pr[q] = Pbase + (size_t)rr * 512 + tg * 64;
            ps[q] = Pbase + (size_t)ss * 512 + 256 + tg * 64;
        }

        // ---- acc init: gather fp16 P_recv + P_send (b1 pre-folded), C-frag layout
        float c1[2][16][4];
#pragma unroll
        for (int b = 0; b < 2; b++) {
            uint4 ra[4], sa[4], rb[4], sb[4];
#pragma unroll
            for (int i = 0; i < 4; i++) {
                ra[i] = ((const uint4*)pr[2 * b])[i];
                sa[i] = ((const uint4*)ps[2 * b])[i];
                rb[i] = ((const uint4*)pr[2 * b + 1])[i];
                sb[i] = ((const uint4*)ps[2 * b + 1])[i];
            }
#pragma unroll
            for (int i = 0; i < 4; i++) {
                const uint32_t* raw = (const uint32_t*)&ra[i];
                const uint32_t* saw = (const uint32_t*)&sa[i];
                const uint32_t* rbw = (const uint32_t*)&rb[i];
                const uint32_t* sbw = (const uint32_t*)&sb[i];
#pragma unroll
                for (int t = 0; t < 4; t++) {
                    int j = 4 * i + t;
                    float2 fa = h2f(raw[t]), fb = h2f(saw[t]);
                    float2 fc = h2f(rbw[t]), fd = h2f(sbw[t]);
                    c1[b][j][0] = fa.x + fb.x;
                    c1[b][j][1] = fa.y + fb.y;
                    c1[b][j][2] = fc.x + fd.x;
                    c1[b][j][3] = fc.y + fd.y;
                }
            }
        }

        // ---- A1 fragments from edata (bf16 hi/lo split)
        uint32_t ah[2][4][4], al[2][4][4];
#pragma unroll
        for (int b = 0; b < 2; b++) {
            const float* x0 = edata + (size_t)em[2 * b] * 64;
            const float* x1 = edata + (size_t)em[2 * b + 1] * 64;
#pragma unroll
            for (int s = 0; s < 4; s++) {
                int k = 16 * s + 2 * tg;
                float2 v0 = *(const float2*)(x0 + k);
                float2 v1 = *(const float2*)(x1 + k);
                float2 v2 = *(const float2*)(x0 + k + 8);
                float2 v3 = *(const float2*)(x1 + k + 8);
                split2(v0.x, v0.y, ah[b][s][0], al[b][s][0]);
                split2(v1.x, v1.y, ah[b][s][1], al[b][s][1]);
                split2(v2.x, v2.y, ah[b][s][2], al[b][s][2]);
                split2(v3.x, v3.y, ah[b][s][3], al[b][s][3]);
            }
        }

        // ---- GEMM1: c1 += Xh@W1h + Xl@W1h + Xh@W1l  (each uint4 feeds 6 mmas)
#pragma unroll
        for (int j = 0; j < 16; j++) {
#pragma unroll
            for (int s = 0; s < 4; s++) {
                uint4 f = w1f[(j * 4 + s) * 32 + lid];
#pragma unroll
                for (int b = 0; b < 2; b++) {
                    mma_bf16(c1[b][j], ah[b][s], f.x, f.y);
                    mma_bf16(c1[b][j], al[b][s], f.x, f.y);
                    mma_bf16(c1[b][j], ah[b][s], f.z, f.w);
                }
            }
        }

        // ---- relu + bf16 split: C-frag -> A-frag (register-local)
        uint32_t a2h[2][8][4], a2l[2][8][4];
#pragma unroll
        for (int b = 0; b < 2; b++) {
#pragma unroll
            for (int t = 0; t < 8; t++) {
                split2(fmaxf(c1[b][2 * t][0], 0.0f),     fmaxf(c1[b][2 * t][1], 0.0f),
                       a2h[b][t][0], a2l[b][t][0]);
                split2(fmaxf(c1[b][2 * t][2], 0.0f),     fmaxf(c1[b][2 * t][3], 0.0f),
                       a2h[b][t][1], a2l[b][t][1]);
                split2(fmaxf(c1[b][2 * t + 1][0], 0.0f), fmaxf(c1[b][2 * t + 1][1], 0.0f),
                       a2h[b][t][2], a2l[b][t][2]);
                split2(fmaxf(c1[b][2 * t + 1][2], 0.0f), fmaxf(c1[b][2 * t + 1][3], 0.0f),
                       a2h[b][t][3], a2l[b][t][3]);
            }
        }

        // ---- acc2 init from b2
        float d2[2][8][4];
#pragma unroll
        for (int j = 0; j < 8; j++) {
            float2 bb = *(const float2*)(b2f + 8 * j + 2 * tg);
#pragma unroll
            for (int b = 0; b < 2; b++) {
                d2[b][j][0] = bb.x; d2[b][j][1] = bb.y;
                d2[b][j][2] = bb.x; d2[b][j][3] = bb.y;
            }
        }

        // ---- GEMM2: d2 += Hh@W2h + Hl@W2h + Hh@W2l
#pragma unroll
        for (int j = 0; j < 8; j++) {
#pragma unroll
            for (int t = 0; t < 8; t++) {
                uint4 f = w2f[(j * 8 + t) * 32 + lid];
#pragma unroll
                for (int b = 0; b < 2; b++) {
                    mma_bf16(d2[b][j], a2h[b][t], f.x, f.y);
                    mma_bf16(d2[b][j], a2l[b][t], f.x, f.y);
                    mma_bf16(d2[b][j], a2h[b][t], f.z, f.w);
                }
            }
        }

        // ---- store
#pragma unroll
        for (int b = 0; b < 2; b++) {
            float* o0 = out + (size_t)em[2 * b] * 64;
            float* o1 = out + (size_t)em[2 * b + 1] * 64;
#pragma unroll
            for (int j = 0; j < 8; j++) {
                int col = 8 * j + 2 * tg;
                *(float2*)(o0 + col) = make_float2(d2[b][j][0], d2[b][j][1]);
                *(float2*)(o1 + col) = make_float2(d2[b][j][2], d2[b][j][3]);
            }
        }
    }
}

// ---------------------------------------------------------------------------
extern "C" void kernel_launch(void* const* d_in, const int* in_sizes, int n_in,
                              void* d_out, int out_size) {
    const float* edata     = (const float*)d_in[0];
    const float* vfeat     = (const float*)d_in[1];
    const float* W1        = (const float*)d_in[2];
    const float* b1        = (const float*)d_in[3];
    const float* W2        = (const float*)d_in[4];
    const float* b2        = (const float*)d_in[5];
    const void*  senders   = d_in[6];
    const void*  receivers = d_in[7];
    float* out = (float*)d_out;
    (void)in_sizes; (void)n_in; (void)out_size;

    const int pc_smem = (64 * 256 + PC_TILE * 64) * 4;             // 81920 B
    const int e_smem  = 2 * 2048 * 16 + 64 * 4 + 16;               // 65808 B

    cudaFuncSetAttribute(precompute_kernel,
                         cudaFuncAttributeMaxDynamicSharedMemorySize, pc_smem);
    cudaFuncSetAttribute(edge_kernel,
                         cudaFuncAttributeMaxDynamicSharedMemorySize, e_smem);

    int sms = 0;
    cudaDeviceGetAttribute(&sms, cudaDevAttrMultiProcessorCount, 0);
    if (sms <= 0) sms = 148;

    precompute_kernel<<<(N_NODES + PC_TILE - 1) / PC_TILE, 256, pc_smem>>>(vfeat, W1, b1);
    edge_kernel<<<sms, 256, e_smem>>>(edata, W1, W2, b2, senders, receivers, out);
}

// round 8
// speedup vs baseline: 1.8844x; 1.1581x over previous
#include <cuda_runtime.h>
#include <cuda_bf16.h>
#include <cuda_fp16.h>
#include <cstdint>

#define N_NODES   50000
#define N_EDGES_C 1600000
#define TILE_E    384
#define PC_TILE   64

// Scratch: per-node fp16 [vfeat@W1_recv + 0.5*b1 | vfeat@W1_send + 0.5*b1],
// permuted fragment-major: half index = h*128 + tg*32 + j*2 + c
// (h: 0=recv,1=send; tg=(col>>1)&3; j=col>>3; c=col&1), 50000 x 256 fp16 (25.6 MB)
__device__ __half g_Ph[(size_t)N_NODES * 256];

// ============================ helpers ============================
__device__ __forceinline__ void mma_f16(float* c, const uint32_t* a, uint32_t b0, uint32_t b1) {
    asm volatile("mma.sync.aligned.m16n8k16.row.col.f32.f16.f16.f32 "
        "{%0,%1,%2,%3}, {%4,%5,%6,%7}, {%8,%9}, {%0,%1,%2,%3};"
        : "+f"(c[0]), "+f"(c[1]), "+f"(c[2]), "+f"(c[3])
        : "r"(a[0]), "r"(a[1]), "r"(a[2]), "r"(a[3]), "r"(b0), "r"(b1));
}

__device__ __forceinline__ uint32_t pack_h2(float x, float y) {
    __half2 h = __floats2half2_rn(x, y);
    return *reinterpret_cast<uint32_t*>(&h);
}
// fp16 weight hi/lo split (w = hi + lo, residual ~2^-21)
__device__ __forceinline__ void wsplit(float w0, float w1, uint32_t& hi, uint32_t& lo) {
    float h0 = __half2float(__float2half_rn(w0));
    float h1 = __half2float(__float2half_rn(w1));
    hi = pack_h2(h0, h1);
    lo = pack_h2(w0 - h0, w1 - h1);
}

__device__ __forceinline__ float2 h2f(uint32_t u) {
    __half2 h = *reinterpret_cast<__half2*>(&u);
    return __half22float2(h);
}

// ---------------------------------------------------------------------------
// Precompute P[n] = [vfeat[n]@W1_recv + 0.5 b1 | vfeat[n]@W1_send + 0.5 b1],
// stored fp16 in fragment-permuted order.
// ---------------------------------------------------------------------------
__global__ void __launch_bounds__(256)
precompute_kernel(const float* __restrict__ vfeat, const float* __restrict__ W1,
                  const float* __restrict__ b1) {
    extern __shared__ char smraw[];
    float* sW = (float*)smraw;               // [64][256]
    float* sV = (float*)smraw + 64 * 256;    // [64][64]
    const int tid = threadIdx.x;
    const int n0  = blockIdx.x * PC_TILE;

    for (int idx = tid; idx < 64 * 256; idx += 256) {
        int k = idx >> 8, j = idx & 255;
        sW[idx] = (j < 128) ? W1[(64 + k) * 128 + j]
                            : W1[(128 + k) * 128 + (j - 128)];
    }
    for (int idx = tid; idx < PC_TILE * 64; idx += 256) {
        int n = idx >> 6;
        sV[idx] = (n0 + n < N_NODES) ? vfeat[(size_t)(n0 + n) * 64 + (idx & 63)] : 0.0f;
    }
    __syncthreads();

    const int tx = tid & 31;
    const int ty = tid >> 5;
    float acc[8][8];
#pragma unroll
    for (int i = 0; i < 8; i++)
#pragma unroll
        for (int j = 0; j < 8; j++) acc[i][j] = 0.0f;

    const float* vb = sV + ty * 8 * 64;
    const float* wb = sW + tx * 8;
#pragma unroll 4
    for (int k = 0; k < 64; ++k) {
        float4 wa = *(const float4*)(wb + k * 256);
        float4 wc = *(const float4*)(wb + k * 256 + 4);
        float wv[8] = {wa.x, wa.y, wa.z, wa.w, wc.x, wc.y, wc.z, wc.w};
#pragma unroll
        for (int i = 0; i < 8; i++) {
            float v = vb[i * 64 + k];
#pragma unroll
            for (int j = 0; j < 8; j++) acc[i][j] += v * wv[j];
        }
    }
    float bh[8];
#pragma unroll
    for (int j = 0; j < 8; j++) bh[j] = 0.5f * b1[(tx * 8 + j) & 127];

#pragma unroll
    for (int i = 0; i < 8; i++) {
        int node = n0 + ty * 8 + i;
        if (node < N_NODES) {
            __half* dst = g_Ph + (size_t)node * 256;
#pragma unroll
            for (int j = 0; j < 8; j++) {
                int C = tx * 8 + j;                 // global output col 0..255
                int h = C >> 7, c = C & 127;
                int jj = c >> 3, tg = (c >> 1) & 3, cc = c & 1;
                dst[h * 128 + tg * 32 + jj * 2 + cc] = __float2half(acc[i][j] + bh[j]);
            }
        }
    }
}

// ---------------------------------------------------------------------------
// Persistent HMMA edge kernel. fp16 2-term weights, fp16 activations,
// M=48 rows/warp (3 m16 blocks), TILE_E=384. GEMM1 chunked over j (4 at a
// time) to bound live accumulators; gather issued per chunk (1 LDG.128 per
// row-half). No __syncthreads in the main loop.
// ---------------------------------------------------------------------------
__global__ void __launch_bounds__(256, 1)
edge_kernel(const float* __restrict__ edata,
            const float* __restrict__ W1,
            const float* __restrict__ W2,
            const float* __restrict__ b2,
            const void*  __restrict__ senders,
            const void*  __restrict__ receivers,
            float* __restrict__ out) {
    extern __shared__ char smraw[];
    uint4* w1f = (uint4*)smraw;              // [16 J][4 s][32 lane] {b0h,b1h,b0l,b1l}
    uint4* w2f = w1f + 2048;                 // [8 j][8 t][32 lane]
    float* b2f = (float*)(w2f + 2048);       // 64
    int*   sFlag = (int*)(b2f + 64);

    const int tid = threadIdx.x;
    const int wid = tid >> 5, lid = tid & 31;
    const int gq  = lid >> 2;     // fragment row
    const int tg  = lid & 3;      // fragment col pair

    if (tid < 32) {
        unsigned hiw = ((const unsigned*)senders)[2 * tid + 1];
        unsigned ball = __ballot_sync(0xffffffffu, hiw == 0u);
        if (tid == 0) *sFlag = (ball == 0xffffffffu);
    }

    // ---- Stage W1 fragments, fragment-ordered, fp16 hi/lo interleaved
    for (int idx = tid; idx < 2048; idx += 256) {
        int lane = idx & 31, s = (idx >> 5) & 3, j = idx >> 7;
        int k = 16 * s + 2 * (lane & 3);
        int n = 8 * j + (lane >> 2);
        uint4 f;
        wsplit(W1[k * 128 + n],       W1[(k + 1) * 128 + n], f.x, f.z);
        wsplit(W1[(k + 8) * 128 + n], W1[(k + 9) * 128 + n], f.y, f.w);
        w1f[idx] = f;
    }
    for (int idx = tid; idx < 2048; idx += 256) {
        int lane = idx & 31, t = (idx >> 5) & 7, j = idx >> 8;
        int k = 16 * t + 2 * (lane & 3);
        int n = 8 * j + (lane >> 2);
        uint4 f;
        wsplit(W2[k * 64 + n],       W2[(k + 1) * 64 + n], f.x, f.z);
        wsplit(W2[(k + 8) * 64 + n], W2[(k + 9) * 64 + n], f.y, f.w);
        w2f[idx] = f;
    }
    if (tid < 64) b2f[tid] = b2[tid];
    __syncthreads();

    const int idx64 = *sFlag;
    const long long* r64 = (const long long*)receivers;
    const int*       r32 = (const int*)receivers;
    const long long* s64 = (const long long*)senders;
    const int*       s32 = (const int*)senders;

    const char* Pbase = (const char*)g_Ph;
    const int ntiles = (N_EDGES_C + TILE_E - 1) / TILE_E;   // 4167 (last partial)

    for (int tile = blockIdx.x; tile < ntiles; tile += gridDim.x) {
        const int base = tile * TILE_E + wid * 48 + gq;
        int em[6];
#pragma unroll
        for (int b = 0; b < 3; b++) { em[2 * b] = base + 16 * b; em[2 * b + 1] = base + 16 * b + 8; }

        const char* pr[6];   // recv row-half base (permuted fp16, +tg*64)
        const char* ps[6];   // send row-half base
#pragma unroll
        for (int q = 0; q < 6; q++) {
            int e = em[q] < N_EDGES_C ? em[q] : (N_EDGES_C - 1);
            int rr = idx64 ? (int)r64[e] : r32[e];
            int ss = idx64 ? (int)s64[e] : s32[e];
            pr[q] = Pbase + (size_t)rr * 512 + tg * 64;
            ps[q] = Pbase + (size_t)ss * 512 + 256 + tg * 64;
        }

        // ---- A1 fragments from edata (fp16 quantize, single term)
        uint32_t a1[3][4][4];
#pragma unroll
        for (int b = 0; b < 3; b++) {
            int e0 = em[2 * b] < N_EDGES_C ? em[2 * b] : (N_EDGES_C - 1);
            int e1 = em[2 * b + 1] < N_EDGES_C ? em[2 * b + 1] : (N_EDGES_C - 1);
            const float* x0 = edata + (size_t)e0 * 64;
            const float* x1 = edata + (size_t)e1 * 64;
#pragma unroll
            for (int s = 0; s < 4; s++) {
                int k = 16 * s + 2 * tg;
                float2 v0 = *(const float2*)(x0 + k);
                float2 v1 = *(const float2*)(x1 + k);
                float2 v2 = *(const float2*)(x0 + k + 8);
                float2 v3 = *(const float2*)(x1 + k + 8);
                a1[b][s][0] = pack_h2(v0.x, v0.y);
                a1[b][s][1] = pack_h2(v1.x, v1.y);
                a1[b][s][2] = pack_h2(v2.x, v2.y);
                a1[b][s][3] = pack_h2(v3.x, v3.y);
            }
        }

        // ---- GEMM1 in 4 chunks of 4 J; produce fp16 A2 fragments
        uint32_t a2[3][8][4];
#pragma unroll
        for (int jc = 0; jc < 4; jc++) {
            float c1[3][4][4];
            // gather chunk: cols J=4jc..4jc+3 are one uint4 per row-half
#pragma unroll
            for (int b = 0; b < 3; b++) {
                uint4 ra = *(const uint4*)(pr[2 * b] + jc * 16);
                uint4 sa = *(const uint4*)(ps[2 * b] + jc * 16);
                uint4 rb = *(const uint4*)(pr[2 * b + 1] + jc * 16);
                uint4 sb = *(const uint4*)(ps[2 * b + 1] + jc * 16);
                const uint32_t* raw = (const uint32_t*)&ra;
                const uint32_t* saw = (const uint32_t*)&sa;
                const uint32_t* rbw = (const uint32_t*)&rb;
                const uint32_t* sbw = (const uint32_t*)&sb;
#pragma unroll
                for (int jj = 0; jj < 4; jj++) {
                    float2 fa = h2f(raw[jj]), fb = h2f(saw[jj]);
                    float2 fc = h2f(rbw[jj]), fd = h2f(sbw[jj]);
                    c1[b][jj][0] = fa.x + fb.x;
                    c1[b][jj][1] = fa.y + fb.y;
                    c1[b][jj][2] = fc.x + fd.x;
                    c1[b][jj][3] = fc.y + fd.y;
                }
            }
            // mmas for this chunk
#pragma unroll
            for (int jj = 0; jj < 4; jj++) {
                int J = 4 * jc + jj;
#pragma unroll
                for (int s = 0; s < 4; s++) {
                    uint4 f = w1f[(J * 4 + s) * 32 + lid];
#pragma unroll
                    for (int b = 0; b < 3; b++) {
                        mma_f16(c1[b][jj], a1[b][s], f.x, f.y);
                        mma_f16(c1[b][jj], a1[b][s], f.z, f.w);
                    }
                }
            }
            // relu + fp16 pack into A2 frags (t = 2jc, 2jc+1)
#pragma unroll
            for (int b = 0; b < 3; b++) {
#pragma unroll
                for (int p = 0; p < 2; p++) {      // pair (jj=2p, 2p+1) -> t=2jc+p
                    int t = 2 * jc + p;
                    a2[b][t][0] = pack_h2(fmaxf(c1[b][2 * p][0], 0.0f),     fmaxf(c1[b][2 * p][1], 0.0f));
                    a2[b][t][1] = pack_h2(fmaxf(c1[b][2 * p][2], 0.0f),     fmaxf(c1[b][2 * p][3], 0.0f));
                    a2[b][t][2] = pack_h2(fmaxf(c1[b][2 * p + 1][0], 0.0f), fmaxf(c1[b][2 * p + 1][1], 0.0f));
                    a2[b][t][3] = pack_h2(fmaxf(c1[b][2 * p + 1][2], 0.0f), fmaxf(c1[b][2 * p + 1][3], 0.0f));
                }
            }
        }

        // ---- GEMM2: d2 = b2 + H@W2hi + H@W2lo
        float d2[3][8][4];
#pragma unroll
        for (int j = 0; j < 8; j++) {
            float2 bb = *(const float2*)(b2f + 8 * j + 2 * tg);
#pragma unroll
            for (int b = 0; b < 3; b++) {
                d2[b][j][0] = bb.x; d2[b][j][1] = bb.y;
                d2[b][j][2] = bb.x; d2[b][j][3] = bb.y;
            }
        }
#pragma unroll
        for (int j = 0; j < 8; j++) {
#pragma unroll
            for (int t = 0; t < 8; t++) {
                uint4 f = w2f[(j * 8 + t) * 32 + lid];
#pragma unroll
                for (int b = 0; b < 3; b++) {
                    mma_f16(d2[b][j], a2[b][t], f.x, f.y);
                    mma_f16(d2[b][j], a2[b][t], f.z, f.w);
                }
            }
        }

        // ---- store (guarded for tail tile)
#pragma unroll
        for (int b = 0; b < 3; b++) {
            if (em[2 * b] < N_EDGES_C) {
                float* o0 = out + (size_t)em[2 * b] * 64;
#pragma unroll
                for (int j = 0; j < 8; j++) {
                    int col = 8 * j + 2 * tg;
                    *(float2*)(o0 + col) = make_float2(d2[b][j][0], d2[b][j][1]);
                }
            }
            if (em[2 * b + 1] < N_EDGES_C) {
                float* o1 = out + (size_t)em[2 * b + 1] * 64;
#pragma unroll
                for (int j = 0; j < 8; j++) {
                    int col = 8 * j + 2 * tg;
                    *(float2*)(o1 + col) = make_float2(d2[b][j][2], d2[b][j][3]);
                }
            }
        }
    }
}

// ---------------------------------------------------------------------------
extern "C" void kernel_launch(void* const* d_in, const int* in_sizes, int n_in,
                              void* d_out, int out_size) {
    const float* edata     = (const float*)d_in[0];
    const float* vfeat     = (const float*)d_in[1];
    const float* W1        = (const float*)d_in[2];
    const float* b1        = (const float*)d_in[3];
    const float* W2        = (const float*)d_in[4];
    const float* b2        = (const float*)d_in[5];
    const void*  senders   = d_in[6];
    const void*  receivers = d_in[7];
    float* out = (float*)d_out;
    (void)in_sizes; (void)n_in; (void)out_size;

    const int pc_smem = (64 * 256 + PC_TILE * 64) * 4;             // 81920 B
    const int e_smem  = 2 * 2048 * 16 + 64 * 4 + 16;               // 65808 B

    cudaFuncSetAttribute(precompute_kernel,
                         cudaFuncAttributeMaxDynamicSharedMemorySize, pc_smem);
    cudaFuncSetAttribute(edge_kernel,
                         cudaFuncAttributeMaxDynamicSharedMemorySize, e_smem);

    int sms = 0;
    cudaDeviceGetAttribute(&sms, cudaDevAttrMultiProcessorCount, 0);
    if (sms <= 0) sms = 148;

    precompute_kernel<<<(N_NODES + PC_TILE - 1) / PC_TILE, 256, pc_smem>>>(vfeat, W1, b1);
    edge_kernel<<<sms, 256, e_smem>>>(edata, W1, W2, b2, senders, receivers, out);
}

// round 9
// speedup vs baseline: 2.3590x; 1.2518x over previous
#include <cuda_runtime.h>
#include <cuda_fp16.h>
#include <cstdint>

#define N_NODES   50000
#define N_EDGES_C 1600000
#define TILE_E    384
#define PC_TILE   64

// Scratch: per-node fp16 [vfeat@W1_recv + 0.5*b1 | vfeat@W1_send + 0.5*b1],
// chunk-major permuted: half index = jc*32 + tg*8 + jj*2 + c  where
// col = 8*(4*jc+jj) + 2*tg + c.  Each (row, jc) chunk is 64 B contiguous.
__device__ __half g_Ph[(size_t)N_NODES * 256];

// ============================ helpers ============================
__device__ __forceinline__ void mma_f16(float* c, const uint32_t* a, uint32_t b0, uint32_t b1) {
    asm volatile("mma.sync.aligned.m16n8k16.row.col.f32.f16.f16.f32 "
        "{%0,%1,%2,%3}, {%4,%5,%6,%7}, {%8,%9}, {%0,%1,%2,%3};"
        : "+f"(c[0]), "+f"(c[1]), "+f"(c[2]), "+f"(c[3])
        : "r"(a[0]), "r"(a[1]), "r"(a[2]), "r"(a[3]), "r"(b0), "r"(b1));
}

__device__ __forceinline__ uint32_t pack_h2(float x, float y) {
    __half2 h = __floats2half2_rn(x, y);
    return *reinterpret_cast<uint32_t*>(&h);
}
__device__ __forceinline__ void wsplit(float w0, float w1, uint32_t& hi, uint32_t& lo) {
    float h0 = __half2float(__float2half_rn(w0));
    float h1 = __half2float(__float2half_rn(w1));
    hi = pack_h2(h0, h1);
    lo = pack_h2(w0 - h0, w1 - h1);
}
__device__ __forceinline__ float2 h2f(uint32_t u) {
    __half2 h = *reinterpret_cast<__half2*>(&u);
    return __half22float2(h);
}

// ---------------------------------------------------------------------------
// Precompute P[n] (fp16, chunk-major permuted layout)
// ---------------------------------------------------------------------------
__global__ void __launch_bounds__(256)
precompute_kernel(const float* __restrict__ vfeat, const float* __restrict__ W1,
                  const float* __restrict__ b1) {
    extern __shared__ char smraw[];
    float* sW = (float*)smraw;               // [64][256]
    float* sV = (float*)smraw + 64 * 256;    // [64][64]
    const int tid = threadIdx.x;
    const int n0  = blockIdx.x * PC_TILE;

    for (int idx = tid; idx < 64 * 256; idx += 256) {
        int k = idx >> 8, j = idx & 255;
        sW[idx] = (j < 128) ? W1[(64 + k) * 128 + j]
                            : W1[(128 + k) * 128 + (j - 128)];
    }
    for (int idx = tid; idx < PC_TILE * 64; idx += 256) {
        int n = idx >> 6;
        sV[idx] = (n0 + n < N_NODES) ? vfeat[(size_t)(n0 + n) * 64 + (idx & 63)] : 0.0f;
    }
    __syncthreads();

    const int tx = tid & 31;
    const int ty = tid >> 5;
    float acc[8][8];
#pragma unroll
    for (int i = 0; i < 8; i++)
#pragma unroll
        for (int j = 0; j < 8; j++) acc[i][j] = 0.0f;

    const float* vb = sV + ty * 8 * 64;
    const float* wb = sW + tx * 8;
#pragma unroll 4
    for (int k = 0; k < 64; ++k) {
        float4 wa = *(const float4*)(wb + k * 256);
        float4 wc = *(const float4*)(wb + k * 256 + 4);
        float wv[8] = {wa.x, wa.y, wa.z, wa.w, wc.x, wc.y, wc.z, wc.w};
#pragma unroll
        for (int i = 0; i < 8; i++) {
            float v = vb[i * 64 + k];
#pragma unroll
            for (int j = 0; j < 8; j++) acc[i][j] += v * wv[j];
        }
    }
    float bh[8];
#pragma unroll
    for (int j = 0; j < 8; j++) bh[j] = 0.5f * b1[(tx * 8 + j) & 127];

#pragma unroll
    for (int i = 0; i < 8; i++) {
        int node = n0 + ty * 8 + i;
        if (node < N_NODES) {
            __half* dst = g_Ph + (size_t)node * 256;
#pragma unroll
            for (int j = 0; j < 8; j++) {
                int C = tx * 8 + j;                 // global output col 0..255
                int h = C >> 7, cl = C & 127;
                int J = cl >> 3, tg = (cl >> 1) & 3, cc = cl & 1;
                int halfidx = (J >> 2) * 32 + tg * 8 + (J & 3) * 2 + cc;
                dst[h * 128 + halfidx] = __float2half(acc[i][j] + bh[j]);
            }
        }
    }
}

// ---------------------------------------------------------------------------
// Persistent HMMA edge kernel. fp16 weights (W1 2-term, W2 1-term), fp16
// activations, M=48 rows/warp, TILE_E=384. GEMM1 chunked over J (4 at a time,
// 64-B contiguous gather per row-chunk). GEMM2 split in 2 halves with
// interleaved stores to bound register pressure.
// ---------------------------------------------------------------------------
__global__ void __launch_bounds__(256, 1)
edge_kernel(const float* __restrict__ edata,
            const float* __restrict__ W1,
            const float* __restrict__ W2,
            const float* __restrict__ b2,
            const void*  __restrict__ senders,
            const void*  __restrict__ receivers,
            float* __restrict__ out) {
    extern __shared__ char smraw[];
    uint4* w1f = (uint4*)smraw;              // [16 J][4 s][32 lane] {b0h,b1h,b0l,b1l}  32 KB
    uint2* w2h = (uint2*)(w1f + 2048);       // [8 j][8 t][32 lane] hi only             16 KB
    float* b2f = (float*)(w2h + 2048);       // 64
    int*   sFlag = (int*)(b2f + 64);

    const int tid = threadIdx.x;
    const int wid = tid >> 5, lid = tid & 31;
    const int gq  = lid >> 2;     // fragment row
    const int tg  = lid & 3;      // fragment col pair

    if (tid < 32) {
        unsigned hiw = ((const unsigned*)senders)[2 * tid + 1];
        unsigned ball = __ballot_sync(0xffffffffu, hiw == 0u);
        if (tid == 0) *sFlag = (ball == 0xffffffffu);
    }

    // ---- Stage W1 fragments (fp16 hi/lo interleaved)
    for (int idx = tid; idx < 2048; idx += 256) {
        int lane = idx & 31, s = (idx >> 5) & 3, j = idx >> 7;
        int k = 16 * s + 2 * (lane & 3);
        int n = 8 * j + (lane >> 2);
        uint4 f;
        wsplit(W1[k * 128 + n],       W1[(k + 1) * 128 + n], f.x, f.z);
        wsplit(W1[(k + 8) * 128 + n], W1[(k + 9) * 128 + n], f.y, f.w);
        w1f[idx] = f;
    }
    // ---- Stage W2 fragments (fp16 hi only)
    for (int idx = tid; idx < 2048; idx += 256) {
        int lane = idx & 31, t = (idx >> 5) & 7, j = idx >> 8;
        int k = 16 * t + 2 * (lane & 3);
        int n = 8 * j + (lane >> 2);
        uint2 f;
        f.x = pack_h2(__half2float(__float2half_rn(W2[k * 64 + n])),
                      __half2float(__float2half_rn(W2[(k + 1) * 64 + n])));
        f.y = pack_h2(__half2float(__float2half_rn(W2[(k + 8) * 64 + n])),
                      __half2float(__float2half_rn(W2[(k + 9) * 64 + n])));
        // store exact fp16 bit patterns
        __half2 h0 = __floats2half2_rn(W2[k * 64 + n], W2[(k + 1) * 64 + n]);
        __half2 h1 = __floats2half2_rn(W2[(k + 8) * 64 + n], W2[(k + 9) * 64 + n]);
        f.x = *reinterpret_cast<uint32_t*>(&h0);
        f.y = *reinterpret_cast<uint32_t*>(&h1);
        w2h[idx] = f;
    }
    if (tid < 64) b2f[tid] = b2[tid];
    __syncthreads();

    const int idx64 = *sFlag;
    const long long* r64 = (const long long*)receivers;
    const int*       r32 = (const int*)receivers;
    const long long* s64 = (const long long*)senders;
    const int*       s32 = (const int*)senders;

    const char* Pbase = (const char*)g_Ph;
    const int ntiles = (N_EDGES_C + TILE_E - 1) / TILE_E;

    for (int tile = blockIdx.x; tile < ntiles; tile += gridDim.x) {
        const int base = tile * TILE_E + wid * 48 + gq;
        int em[6];
#pragma unroll
        for (int b = 0; b < 3; b++) { em[2 * b] = base + 16 * b; em[2 * b + 1] = base + 16 * b + 8; }

        // 32-bit byte offsets into g_Ph (max 50000*512 = 25.6 MB, fits)
        uint32_t offR[6], offS[6];
#pragma unroll
        for (int q = 0; q < 6; q++) {
            int e = em[q] < N_EDGES_C ? em[q] : (N_EDGES_C - 1);
            int rr = idx64 ? (int)r64[e] : r32[e];
            int ss = idx64 ? (int)s64[e] : s32[e];
            offR[q] = (uint32_t)rr * 512u + tg * 16u;
            offS[q] = (uint32_t)ss * 512u + 256u + tg * 16u;
        }

        // ---- A1 fragments from edata (fp16 quantize)
        uint32_t a1[3][4][4];
#pragma unroll
        for (int b = 0; b < 3; b++) {
            int e0 = em[2 * b] < N_EDGES_C ? em[2 * b] : (N_EDGES_C - 1);
            int e1 = em[2 * b + 1] < N_EDGES_C ? em[2 * b + 1] : (N_EDGES_C - 1);
            const float* x0 = edata + (size_t)e0 * 64;
            const float* x1 = edata + (size_t)e1 * 64;
#pragma unroll
            for (int s = 0; s < 4; s++) {
                int k = 16 * s + 2 * tg;
                float2 v0 = *(const float2*)(x0 + k);
                float2 v1 = *(const float2*)(x1 + k);
                float2 v2 = *(const float2*)(x0 + k + 8);
                float2 v3 = *(const float2*)(x1 + k + 8);
                a1[b][s][0] = pack_h2(v0.x, v0.y);
                a1[b][s][1] = pack_h2(v1.x, v1.y);
                a1[b][s][2] = pack_h2(v2.x, v2.y);
                a1[b][s][3] = pack_h2(v3.x, v3.y);
            }
        }

        // ---- GEMM1 in 4 chunks of 4 J; produce fp16 A2 fragments
        uint32_t a2[3][8][4];
#pragma unroll
        for (int jc = 0; jc < 4; jc++) {
            float c1[3][4][4];
            // gather chunk: (row, jc) is one 64-B-contiguous uint4 per tg-lane
#pragma unroll
            for (int b = 0; b < 3; b++) {
                uint4 ra = *(const uint4*)(Pbase + offR[2 * b]     + jc * 64);
                uint4 sa = *(const uint4*)(Pbase + offS[2 * b]     + jc * 64);
                uint4 rb = *(const uint4*)(Pbase + offR[2 * b + 1] + jc * 64);
                uint4 sb = *(const uint4*)(Pbase + offS[2 * b + 1] + jc * 64);
                const uint32_t* raw = (const uint32_t*)&ra;
                const uint32_t* saw = (const uint32_t*)&sa;
                const uint32_t* rbw = (const uint32_t*)&rb;
                const uint32_t* sbw = (const uint32_t*)&sb;
#pragma unroll
                for (int jj = 0; jj < 4; jj++) {
                    float2 fa = h2f(raw[jj]), fb = h2f(saw[jj]);
                    float2 fc = h2f(rbw[jj]), fd = h2f(sbw[jj]);
                    c1[b][jj][0] = fa.x + fb.x;
                    c1[b][jj][1] = fa.y + fb.y;
                    c1[b][jj][2] = fc.x + fd.x;
                    c1[b][jj][3] = fc.y + fd.y;
                }
            }
#pragma unroll
            for (int jj = 0; jj < 4; jj++) {
                int J = 4 * jc + jj;
#pragma unroll
                for (int s = 0; s < 4; s++) {
                    uint4 f = w1f[(J * 4 + s) * 32 + lid];
#pragma unroll
                    for (int b = 0; b < 3; b++) {
                        mma_f16(c1[b][jj], a1[b][s], f.x, f.y);
                        mma_f16(c1[b][jj], a1[b][s], f.z, f.w);
                    }
                }
            }
            // relu + fp16 pack into A2 frags (t = 2jc, 2jc+1)
#pragma unroll
            for (int b = 0; b < 3; b++) {
#pragma unroll
                for (int p = 0; p < 2; p++) {
                    int t = 2 * jc + p;
                    a2[b][t][0] = pack_h2(fmaxf(c1[b][2 * p][0], 0.0f),     fmaxf(c1[b][2 * p][1], 0.0f));
                    a2[b][t][1] = pack_h2(fmaxf(c1[b][2 * p][2], 0.0f),     fmaxf(c1[b][2 * p][3], 0.0f));
                    a2[b][t][2] = pack_h2(fmaxf(c1[b][2 * p + 1][0], 0.0f), fmaxf(c1[b][2 * p + 1][1], 0.0f));
                    a2[b][t][3] = pack_h2(fmaxf(c1[b][2 * p + 1][2], 0.0f), fmaxf(c1[b][2 * p + 1][3], 0.0f));
                }
            }
        }

        // ---- GEMM2 (single-term) in 2 halves of 4 j, stores interleaved
#pragma unroll
        for (int jh = 0; jh < 2; jh++) {
            float d2[3][4][4];
#pragma unroll
            for (int jj = 0; jj < 4; jj++) {
                int j = 4 * jh + jj;
                float2 bb = *(const float2*)(b2f + 8 * j + 2 * tg);
#pragma unroll
                for (int b = 0; b < 3; b++) {
                    d2[b][jj][0] = bb.x; d2[b][jj][1] = bb.y;
                    d2[b][jj][2] = bb.x; d2[b][jj][3] = bb.y;
                }
            }
#pragma unroll
            for (int jj = 0; jj < 4; jj++) {
                int j = 4 * jh + jj;
#pragma unroll
                for (int t = 0; t < 8; t++) {
                    uint2 f = w2h[(j * 8 + t) * 32 + lid];
#pragma unroll
                    for (int b = 0; b < 3; b++)
                        mma_f16(d2[b][jj], a2[b][t], f.x, f.y);
                }
            }
            // stores for output cols 32*jh .. 32*jh+31 (guarded for tail)
#pragma unroll
            for (int b = 0; b < 3; b++) {
                if (em[2 * b] < N_EDGES_C) {
                    float* o0 = out + (size_t)em[2 * b] * 64 + 32 * jh;
#pragma unroll
                    for (int jj = 0; jj < 4; jj++)
                        *(float2*)(o0 + 8 * jj + 2 * tg) = make_float2(d2[b][jj][0], d2[b][jj][1]);
                }
                if (em[2 * b + 1] < N_EDGES_C) {
                    float* o1 = out + (size_t)em[2 * b + 1] * 64 + 32 * jh;
#pragma unroll
                    for (int jj = 0; jj < 4; jj++)
                        *(float2*)(o1 + 8 * jj + 2 * tg) = make_float2(d2[b][jj][2], d2[b][jj][3]);
                }
            }
        }
    }
}

// ---------------------------------------------------------------------------
extern "C" void kernel_launch(void* const* d_in, const int* in_sizes, int n_in,
                              void* d_out, int out_size) {
    const float* edata     = (const float*)d_in[0];
    const float* vfeat     = (const float*)d_in[1];
    const float* W1        = (const float*)d_in[2];
    const float* b1        = (const float*)d_in[3];
    const float* W2        = (const float*)d_in[4];
    const float* b2        = (const float*)d_in[5];
    const void*  senders   = d_in[6];
    const void*  receivers = d_in[7];
    float* out = (float*)d_out;
    (void)in_sizes; (void)n_in; (void)out_size;

    const int pc_smem = (64 * 256 + PC_TILE * 64) * 4;             // 81920 B
    const int e_smem  = 2048 * 16 + 2048 * 8 + 64 * 4 + 16;        // 49424 B

    cudaFuncSetAttribute(precompute_kernel,
                         cudaFuncAttributeMaxDynamicSharedMemorySize, pc_smem);
    cudaFuncSetAttribute(edge_kernel,
                         cudaFuncAttributeMaxDynamicSharedMemorySize, e_smem);

    int sms = 0;
    cudaDeviceGetAttribute(&sms, cudaDevAttrMultiProcessorCount, 0);
    if (sms <= 0) sms = 148;

    precompute_kernel<<<(N_NODES + PC_TILE - 1) / PC_TILE, 256, pc_smem>>>(vfeat, W1, b1);
    edge_kernel<<<sms, 256, e_smem>>>(edata, W1, W2, b2, senders, receivers, out);
}

// round 10
// speedup vs baseline: 2.5226x; 1.0694x over previous
#include <cuda_runtime.h>
#include <cuda_fp16.h>
#include <cstdint>

#define N_NODES   50000
#define N_EDGES_C 1600000
#define TILE_E    384
#define PC_TILE   64

// Scratch: per-node fp16 [vfeat@W1_recv + 0.5*b1 | vfeat@W1_send + 0.5*b1],
// chunk-major permuted: half index = jc*32 + tg*8 + jj*2 + c  where
// col = 8*(4*jc+jj) + 2*tg + c.  Each (row, jc) chunk is 64 B contiguous.
__device__ __half g_Ph[(size_t)N_NODES * 256];

// ============================ helpers ============================
__device__ __forceinline__ void mma_f16(float* c, const uint32_t* a, uint32_t b0, uint32_t b1) {
    asm volatile("mma.sync.aligned.m16n8k16.row.col.f32.f16.f16.f32 "
        "{%0,%1,%2,%3}, {%4,%5,%6,%7}, {%8,%9}, {%0,%1,%2,%3};"
        : "+f"(c[0]), "+f"(c[1]), "+f"(c[2]), "+f"(c[3])
        : "r"(a[0]), "r"(a[1]), "r"(a[2]), "r"(a[3]), "r"(b0), "r"(b1));
}

__device__ __forceinline__ uint32_t pack_h2(float x, float y) {
    __half2 h = __floats2half2_rn(x, y);
    return *reinterpret_cast<uint32_t*>(&h);
}
__device__ __forceinline__ float2 h2f(uint32_t u) {
    __half2 h = *reinterpret_cast<__half2*>(&u);
    return __half22float2(h);
}

// ---------------------------------------------------------------------------
// Precompute P[n] (fp16, chunk-major permuted layout)
// ---------------------------------------------------------------------------
__global__ void __launch_bounds__(256)
precompute_kernel(const float* __restrict__ vfeat, const float* __restrict__ W1,
                  const float* __restrict__ b1) {
    extern __shared__ char smraw[];
    float* sW = (float*)smraw;               // [64][256]
    float* sV = (float*)smraw + 64 * 256;    // [64][64]
    const int tid = threadIdx.x;
    const int n0  = blockIdx.x * PC_TILE;

    for (int idx = tid; idx < 64 * 256; idx += 256) {
        int k = idx >> 8, j = idx & 255;
        sW[idx] = (j < 128) ? W1[(64 + k) * 128 + j]
                            : W1[(128 + k) * 128 + (j - 128)];
    }
    for (int idx = tid; idx < PC_TILE * 64; idx += 256) {
        int n = idx >> 6;
        sV[idx] = (n0 + n < N_NODES) ? vfeat[(size_t)(n0 + n) * 64 + (idx & 63)] : 0.0f;
    }
    __syncthreads();

    const int tx = tid & 31;
    const int ty = tid >> 5;
    float acc[8][8];
#pragma unroll
    for (int i = 0; i < 8; i++)
#pragma unroll
        for (int j = 0; j < 8; j++) acc[i][j] = 0.0f;

    const float* vb = sV + ty * 8 * 64;
    const float* wb = sW + tx * 8;
#pragma unroll 4
    for (int k = 0; k < 64; ++k) {
        float4 wa = *(const float4*)(wb + k * 256);
        float4 wc = *(const float4*)(wb + k * 256 + 4);
        float wv[8] = {wa.x, wa.y, wa.z, wa.w, wc.x, wc.y, wc.z, wc.w};
#pragma unroll
        for (int i = 0; i < 8; i++) {
            float v = vb[i * 64 + k];
#pragma unroll
            for (int j = 0; j < 8; j++) acc[i][j] += v * wv[j];
        }
    }
    float bh[8];
#pragma unroll
    for (int j = 0; j < 8; j++) bh[j] = 0.5f * b1[(tx * 8 + j) & 127];

#pragma unroll
    for (int i = 0; i < 8; i++) {
        int node = n0 + ty * 8 + i;
        if (node < N_NODES) {
            __half* dst = g_Ph + (size_t)node * 256;
#pragma unroll
            for (int j = 0; j < 8; j++) {
                int C = tx * 8 + j;                 // global output col 0..255
                int h = C >> 7, cl = C & 127;
                int J = cl >> 3, tg = (cl >> 1) & 3, cc = cl & 1;
                int halfidx = (J >> 2) * 32 + tg * 8 + (J & 3) * 2 + cc;
                dst[h * 128 + halfidx] = __float2half(acc[i][j] + bh[j]);
            }
        }
    }
}

// ---------------------------------------------------------------------------
// Persistent HMMA edge kernel. fp16 single-term weights (W1 hi, W2 hi), fp16
// activations, M=48 rows/warp, TILE_E=384. GEMM1 chunked over J (4 at a time,
// 64-B contiguous gather per row-chunk). GEMM2 split in 2 halves with
// interleaved stores.
// ---------------------------------------------------------------------------
__global__ void __launch_bounds__(256, 1)
edge_kernel(const float* __restrict__ edata,
            const float* __restrict__ W1,
            const float* __restrict__ W2,
            const float* __restrict__ b2,
            const void*  __restrict__ senders,
            const void*  __restrict__ receivers,
            float* __restrict__ out) {
    extern __shared__ char smraw[];
    uint2* w1h = (uint2*)smraw;              // [16 J][4 s][32 lane] hi   16 KB
    uint2* w2h = (uint2*)(w1h + 2048);       // [8 j][8 t][32 lane] hi    16 KB
    float* b2f = (float*)(w2h + 2048);       // 64
    int*   sFlag = (int*)(b2f + 64);

    const int tid = threadIdx.x;
    const int wid = tid >> 5, lid = tid & 31;
    const int gq  = lid >> 2;     // fragment row
    const int tg  = lid & 3;      // fragment col pair

    if (tid < 32) {
        unsigned hiw = ((const unsigned*)senders)[2 * tid + 1];
        unsigned ball = __ballot_sync(0xffffffffu, hiw == 0u);
        if (tid == 0) *sFlag = (ball == 0xffffffffu);
    }

    // ---- Stage W1 fragments (fp16 hi only)
    for (int idx = tid; idx < 2048; idx += 256) {
        int lane = idx & 31, s = (idx >> 5) & 3, j = idx >> 7;
        int k = 16 * s + 2 * (lane & 3);
        int n = 8 * j + (lane >> 2);
        uint2 f;
        f.x = pack_h2(W1[k * 128 + n],       W1[(k + 1) * 128 + n]);
        f.y = pack_h2(W1[(k + 8) * 128 + n], W1[(k + 9) * 128 + n]);
        w1h[idx] = f;
    }
    // ---- Stage W2 fragments (fp16 hi only)
    for (int idx = tid; idx < 2048; idx += 256) {
        int lane = idx & 31, t = (idx >> 5) & 7, j = idx >> 8;
        int k = 16 * t + 2 * (lane & 3);
        int n = 8 * j + (lane >> 2);
        uint2 f;
        f.x = pack_h2(W2[k * 64 + n],       W2[(k + 1) * 64 + n]);
        f.y = pack_h2(W2[(k + 8) * 64 + n], W2[(k + 9) * 64 + n]);
        w2h[idx] = f;
    }
    if (tid < 64) b2f[tid] = b2[tid];
    __syncthreads();

    const int idx64 = *sFlag;
    const long long* r64 = (const long long*)receivers;
    const int*       r32 = (const int*)receivers;
    const long long* s64 = (const long long*)senders;
    const int*       s32 = (const int*)senders;

    const char* Pbase = (const char*)g_Ph;
    const int ntiles = (N_EDGES_C + TILE_E - 1) / TILE_E;

    for (int tile = blockIdx.x; tile < ntiles; tile += gridDim.x) {
        const int base = tile * TILE_E + wid * 48 + gq;
        int em[6];
#pragma unroll
        for (int b = 0; b < 3; b++) { em[2 * b] = base + 16 * b; em[2 * b + 1] = base + 16 * b + 8; }

        uint32_t offR[6], offS[6];
#pragma unroll
        for (int q = 0; q < 6; q++) {
            int e = em[q] < N_EDGES_C ? em[q] : (N_EDGES_C - 1);
            int rr = idx64 ? (int)r64[e] : r32[e];
            int ss = idx64 ? (int)s64[e] : s32[e];
            offR[q] = (uint32_t)rr * 512u + tg * 16u;
            offS[q] = (uint32_t)ss * 512u + 256u + tg * 16u;
        }

        // ---- A1 fragments from edata (fp16 quantize)
        uint32_t a1[3][4][4];
#pragma unroll
        for (int b = 0; b < 3; b++) {
            int e0 = em[2 * b] < N_EDGES_C ? em[2 * b] : (N_EDGES_C - 1);
            int e1 = em[2 * b + 1] < N_EDGES_C ? em[2 * b + 1] : (N_EDGES_C - 1);
            const float* x0 = edata + (size_t)e0 * 64;
            const float* x1 = edata + (size_t)e1 * 64;
#pragma unroll
            for (int s = 0; s < 4; s++) {
                int k = 16 * s + 2 * tg;
                float2 v0 = *(const float2*)(x0 + k);
                float2 v1 = *(const float2*)(x1 + k);
                float2 v2 = *(const float2*)(x0 + k + 8);
                float2 v3 = *(const float2*)(x1 + k + 8);
                a1[b][s][0] = pack_h2(v0.x, v0.y);
                a1[b][s][1] = pack_h2(v1.x, v1.y);
                a1[b][s][2] = pack_h2(v2.x, v2.y);
                a1[b][s][3] = pack_h2(v3.x, v3.y);
            }
        }

        // ---- GEMM1 in 4 chunks of 4 J; produce fp16 A2 fragments
        uint32_t a2[3][8][4];
#pragma unroll
        for (int jc = 0; jc < 4; jc++) {
            float c1[3][4][4];
#pragma unroll
            for (int b = 0; b < 3; b++) {
                uint4 ra = *(const uint4*)(Pbase + offR[2 * b]     + jc * 64);
                uint4 sa = *(const uint4*)(Pbase + offS[2 * b]     + jc * 64);
                uint4 rb = *(const uint4*)(Pbase + offR[2 * b + 1] + jc * 64);
                uint4 sb = *(const uint4*)(Pbase + offS[2 * b + 1] + jc * 64);
                const uint32_t* raw = (const uint32_t*)&ra;
                const uint32_t* saw = (const uint32_t*)&sa;
                const uint32_t* rbw = (const uint32_t*)&rb;
                const uint32_t* sbw = (const uint32_t*)&sb;
#pragma unroll
                for (int jj = 0; jj < 4; jj++) {
                    float2 fa = h2f(raw[jj]), fb = h2f(saw[jj]);
                    float2 fc = h2f(rbw[jj]), fd = h2f(sbw[jj]);
                    c1[b][jj][0] = fa.x + fb.x;
                    c1[b][jj][1] = fa.y + fb.y;
                    c1[b][jj][2] = fc.x + fd.x;
                    c1[b][jj][3] = fc.y + fd.y;
                }
            }
#pragma unroll
            for (int jj = 0; jj < 4; jj++) {
                int J = 4 * jc + jj;
#pragma unroll
                for (int s = 0; s < 4; s++) {
                    uint2 f = w1h[(J * 4 + s) * 32 + lid];
#pragma unroll
                    for (int b = 0; b < 3; b++)
                        mma_f16(c1[b][jj], a1[b][s], f.x, f.y);
                }
            }
            // relu + fp16 pack into A2 frags (t = 2jc, 2jc+1)
#pragma unroll
            for (int b = 0; b < 3; b++) {
#pragma unroll
                for (int p = 0; p < 2; p++) {
                    int t = 2 * jc + p;
                    a2[b][t][0] = pack_h2(fmaxf(c1[b][2 * p][0], 0.0f),     fmaxf(c1[b][2 * p][1], 0.0f));
                    a2[b][t][1] = pack_h2(fmaxf(c1[b][2 * p][2], 0.0f),     fmaxf(c1[b][2 * p][3], 0.0f));
                    a2[b][t][2] = pack_h2(fmaxf(c1[b][2 * p + 1][0], 0.0f), fmaxf(c1[b][2 * p + 1][1], 0.0f));
                    a2[b][t][3] = pack_h2(fmaxf(c1[b][2 * p + 1][2], 0.0f), fmaxf(c1[b][2 * p + 1][3], 0.0f));
                }
            }
        }

        // ---- GEMM2 (single-term) in 2 halves of 4 j, stores interleaved
#pragma unroll
        for (int jh = 0; jh < 2; jh++) {
            float d2[3][4][4];
#pragma unroll
            for (int jj = 0; jj < 4; jj++) {
                int j = 4 * jh + jj;
                float2 bb = *(const float2*)(b2f + 8 * j + 2 * tg);
#pragma unroll
                for (int b = 0; b < 3; b++) {
                    d2[b][jj][0] = bb.x; d2[b][jj][1] = bb.y;
                    d2[b][jj][2] = bb.x; d2[b][jj][3] = bb.y;
                }
            }
#pragma unroll
            for (int jj = 0; jj < 4; jj++) {
                int j = 4 * jh + jj;
#pragma unroll
                for (int t = 0; t < 8; t++) {
                    uint2 f = w2h[(j * 8 + t) * 32 + lid];
#pragma unroll
                    for (int b = 0; b < 3; b++)
                        mma_f16(d2[b][jj], a2[b][t], f.x, f.y);
                }
            }
#pragma unroll
            for (int b = 0; b < 3; b++) {
                if (em[2 * b] < N_EDGES_C) {
                    float* o0 = out + (size_t)em[2 * b] * 64 + 32 * jh;
#pragma unroll
                    for (int jj = 0; jj < 4; jj++)
                        *(float2*)(o0 + 8 * jj + 2 * tg) = make_float2(d2[b][jj][0], d2[b][jj][1]);
                }
                if (em[2 * b + 1] < N_EDGES_C) {
                    float* o1 = out + (size_t)em[2 * b + 1] * 64 + 32 * jh;
#pragma unroll
                    for (int jj = 0; jj < 4; jj++)
                        *(float2*)(o1 + 8 * jj + 2 * tg) = make_float2(d2[b][jj][2], d2[b][jj][3]);
                }
            }
        }
    }
}

// ---------------------------------------------------------------------------
extern "C" void kernel_launch(void* const* d_in, const int* in_sizes, int n_in,
                              void* d_out, int out_size) {
    const float* edata     = (const float*)d_in[0];
    const float* vfeat     = (const float*)d_in[1];
    const float* W1        = (const float*)d_in[2];
    const float* b1        = (const float*)d_in[3];
    const float* W2        = (const float*)d_in[4];
    const float* b2        = (const float*)d_in[5];
    const void*  senders   = d_in[6];
    const void*  receivers = d_in[7];
    float* out = (float*)d_out;
    (void)in_sizes; (void)n_in; (void)out_size;

    const int pc_smem = (64 * 256 + PC_TILE * 64) * 4;             // 81920 B
    const int e_smem  = 2048 * 8 * 2 + 64 * 4 + 16;                // 33040 B

    cudaFuncSetAttribute(precompute_kernel,
                         cudaFuncAttributeMaxDynamicSharedMemorySize, pc_smem);
    cudaFuncSetAttribute(edge_kernel,
                         cudaFuncAttributeMaxDynamicSharedMemorySize, e_smem);

    int sms = 0;
    cudaDeviceGetAttribute(&sms, cudaDevAttrMultiProcessorCount, 0);
    if (sms <= 0) sms = 148;

    precompute_kernel<<<(N_NODES + PC_TILE - 1) / PC_TILE, 256, pc_smem>>>(vfeat, W1, b1);
    edge_kernel<<<sms, 256, e_smem>>>(edata, W1, W2, b2, senders, receivers, out);
}

// round 11
// speedup vs baseline: 2.5553x; 1.0130x over previous
#include <cuda_runtime.h>
#include <cuda_fp16.h>
#include <cstdint>

#define N_NODES   50000
#define N_EDGES_C 1600000
#define TILE_E    256
#define NT        512
#define PC_TILE   64

// Scratch: per-node fp16 [vfeat@W1_recv + 0.5*b1 | vfeat@W1_send + 0.5*b1],
// chunk-major permuted: half index = jc*32 + tg*8 + jj*2 + c  where
// col = 8*(4*jc+jj) + 2*tg + c.  Each (row, jc) chunk is 64 B contiguous.
__device__ __half g_Ph[(size_t)N_NODES * 256];

// ============================ helpers ============================
__device__ __forceinline__ void mma_f16(float* c, const uint32_t* a, uint32_t b0, uint32_t b1) {
    asm volatile("mma.sync.aligned.m16n8k16.row.col.f32.f16.f16.f32 "
        "{%0,%1,%2,%3}, {%4,%5,%6,%7}, {%8,%9}, {%0,%1,%2,%3};"
        : "+f"(c[0]), "+f"(c[1]), "+f"(c[2]), "+f"(c[3])
        : "r"(a[0]), "r"(a[1]), "r"(a[2]), "r"(a[3]), "r"(b0), "r"(b1));
}

__device__ __forceinline__ uint32_t pack_h2(float x, float y) {
    __half2 h = __floats2half2_rn(x, y);
    return *reinterpret_cast<uint32_t*>(&h);
}
__device__ __forceinline__ float2 h2f(uint32_t u) {
    __half2 h = *reinterpret_cast<__half2*>(&u);
    return __half22float2(h);
}

// ---------------------------------------------------------------------------
// Precompute P[n] (fp16, chunk-major permuted layout)
// ---------------------------------------------------------------------------
__global__ void __launch_bounds__(256)
precompute_kernel(const float* __restrict__ vfeat, const float* __restrict__ W1,
                  const float* __restrict__ b1) {
    extern __shared__ char smraw[];
    float* sW = (float*)smraw;               // [64][256]
    float* sV = (float*)smraw + 64 * 256;    // [64][64]
    const int tid = threadIdx.x;
    const int n0  = blockIdx.x * PC_TILE;

    for (int idx = tid; idx < 64 * 256; idx += 256) {
        int k = idx >> 8, j = idx & 255;
        sW[idx] = (j < 128) ? W1[(64 + k) * 128 + j]
                            : W1[(128 + k) * 128 + (j - 128)];
    }
    for (int idx = tid; idx < PC_TILE * 64; idx += 256) {
        int n = idx >> 6;
        sV[idx] = (n0 + n < N_NODES) ? vfeat[(size_t)(n0 + n) * 64 + (idx & 63)] : 0.0f;
    }
    __syncthreads();

    const int tx = tid & 31;
    const int ty = tid >> 5;
    float acc[8][8];
#pragma unroll
    for (int i = 0; i < 8; i++)
#pragma unroll
        for (int j = 0; j < 8; j++) acc[i][j] = 0.0f;

    const float* vb = sV + ty * 8 * 64;
    const float* wb = sW + tx * 8;
#pragma unroll 4
    for (int k = 0; k < 64; ++k) {
        float4 wa = *(const float4*)(wb + k * 256);
        float4 wc = *(const float4*)(wb + k * 256 + 4);
        float wv[8] = {wa.x, wa.y, wa.z, wa.w, wc.x, wc.y, wc.z, wc.w};
#pragma unroll
        for (int i = 0; i < 8; i++) {
            float v = vb[i * 64 + k];
#pragma unroll
            for (int j = 0; j < 8; j++) acc[i][j] += v * wv[j];
        }
    }
    float bh[8];
#pragma unroll
    for (int j = 0; j < 8; j++) bh[j] = 0.5f * b1[(tx * 8 + j) & 127];

#pragma unroll
    for (int i = 0; i < 8; i++) {
        int node = n0 + ty * 8 + i;
        if (node < N_NODES) {
            __half* dst = g_Ph + (size_t)node * 256;
#pragma unroll
            for (int j = 0; j < 8; j++) {
                int C = tx * 8 + j;                 // global output col 0..255
                int h = C >> 7, cl = C & 127;
                int J = cl >> 3, tg = (cl >> 1) & 3, cc = cl & 1;
                int halfidx = (J >> 2) * 32 + tg * 8 + (J & 3) * 2 + cc;
                dst[h * 128 + halfidx] = __float2half(acc[i][j] + bh[j]);
            }
        }
    }
}

// ---------------------------------------------------------------------------
// Persistent HMMA edge kernel. fp16 single-term weights, fp16 activations.
// 512 threads (16 warps)/CTA, M=16 rows/warp, TILE_E=256/CTA-iter.
// Low register footprint (~100 live) -> 16 warps/SM for latency hiding.
// ---------------------------------------------------------------------------
__global__ void __launch_bounds__(NT, 1)
edge_kernel(const float* __restrict__ edata,
            const float* __restrict__ W1,
            const float* __restrict__ W2,
            const float* __restrict__ b2,
            const void*  __restrict__ senders,
            const void*  __restrict__ receivers,
            float* __restrict__ out) {
    extern __shared__ char smraw[];
    uint2* w1h = (uint2*)smraw;              // [16 J][4 s][32 lane] hi   16 KB
    uint2* w2h = (uint2*)(w1h + 2048);       // [8 j][8 t][32 lane] hi    16 KB
    float* b2f = (float*)(w2h + 2048);       // 64
    int*   sFlag = (int*)(b2f + 64);

    const int tid = threadIdx.x;
    const int wid = tid >> 5, lid = tid & 31;
    const int gq  = lid >> 2;     // fragment row
    const int tg  = lid & 3;      // fragment col pair

    if (tid < 32) {
        unsigned hiw = ((const unsigned*)senders)[2 * tid + 1];
        unsigned ball = __ballot_sync(0xffffffffu, hiw == 0u);
        if (tid == 0) *sFlag = (ball == 0xffffffffu);
    }

    // ---- Stage W1 fragments (fp16 hi only)
    for (int idx = tid; idx < 2048; idx += NT) {
        int lane = idx & 31, s = (idx >> 5) & 3, j = idx >> 7;
        int k = 16 * s + 2 * (lane & 3);
        int n = 8 * j + (lane >> 2);
        uint2 f;
        f.x = pack_h2(W1[k * 128 + n],       W1[(k + 1) * 128 + n]);
        f.y = pack_h2(W1[(k + 8) * 128 + n], W1[(k + 9) * 128 + n]);
        w1h[idx] = f;
    }
    // ---- Stage W2 fragments (fp16 hi only)
    for (int idx = tid; idx < 2048; idx += NT) {
        int lane = idx & 31, t = (idx >> 5) & 7, j = idx >> 8;
        int k = 16 * t + 2 * (lane & 3);
        int n = 8 * j + (lane >> 2);
        uint2 f;
        f.x = pack_h2(W2[k * 64 + n],       W2[(k + 1) * 64 + n]);
        f.y = pack_h2(W2[(k + 8) * 64 + n], W2[(k + 9) * 64 + n]);
        w2h[idx] = f;
    }
    if (tid < 64) b2f[tid] = b2[tid];
    __syncthreads();

    const int idx64 = *sFlag;
    const long long* r64 = (const long long*)receivers;
    const int*       r32 = (const int*)receivers;
    const long long* s64 = (const long long*)senders;
    const int*       s32 = (const int*)senders;

    const char* Pbase = (const char*)g_Ph;
    const int ntiles = (N_EDGES_C + TILE_E - 1) / TILE_E;

    for (int tile = blockIdx.x; tile < ntiles; tile += gridDim.x) {
        const int base = tile * TILE_E + wid * 16 + gq;
        const int em0 = base, em1 = base + 8;
        const int e0c = em0 < N_EDGES_C ? em0 : (N_EDGES_C - 1);
        const int e1c = em1 < N_EDGES_C ? em1 : (N_EDGES_C - 1);

        // 32-bit byte offsets into g_Ph
        uint32_t offR0, offS0, offR1, offS1;
        {
            int rr0 = idx64 ? (int)r64[e0c] : r32[e0c];
            int ss0 = idx64 ? (int)s64[e0c] : s32[e0c];
            int rr1 = idx64 ? (int)r64[e1c] : r32[e1c];
            int ss1 = idx64 ? (int)s64[e1c] : s32[e1c];
            offR0 = (uint32_t)rr0 * 512u + tg * 16u;
            offS0 = (uint32_t)ss0 * 512u + 256u + tg * 16u;
            offR1 = (uint32_t)rr1 * 512u + tg * 16u;
            offS1 = (uint32_t)ss1 * 512u + 256u + tg * 16u;
        }

        // ---- A1 fragments from edata (fp16 quantize)
        uint32_t a1[4][4];
        {
            const float* x0 = edata + (size_t)e0c * 64;
            const float* x1 = edata + (size_t)e1c * 64;
#pragma unroll
            for (int s = 0; s < 4; s++) {
                int k = 16 * s + 2 * tg;
                float2 v0 = *(const float2*)(x0 + k);
                float2 v1 = *(const float2*)(x1 + k);
                float2 v2 = *(const float2*)(x0 + k + 8);
                float2 v3 = *(const float2*)(x1 + k + 8);
                a1[s][0] = pack_h2(v0.x, v0.y);
                a1[s][1] = pack_h2(v1.x, v1.y);
                a1[s][2] = pack_h2(v2.x, v2.y);
                a1[s][3] = pack_h2(v3.x, v3.y);
            }
        }

        // ---- GEMM1 in 4 chunks of 4 J; produce fp16 A2 fragments
        uint32_t a2[8][4];
#pragma unroll
        for (int jc = 0; jc < 4; jc++) {
            float c1[4][4];
            {
                uint4 ra = *(const uint4*)(Pbase + offR0 + jc * 64);
                uint4 sa = *(const uint4*)(Pbase + offS0 + jc * 64);
                uint4 rb = *(const uint4*)(Pbase + offR1 + jc * 64);
                uint4 sb = *(const uint4*)(Pbase + offS1 + jc * 64);
                const uint32_t* raw = (const uint32_t*)&ra;
                const uint32_t* saw = (const uint32_t*)&sa;
                const uint32_t* rbw = (const uint32_t*)&rb;
                const uint32_t* sbw = (const uint32_t*)&sb;
#pragma unroll
                for (int jj = 0; jj < 4; jj++) {
                    float2 fa = h2f(raw[jj]), fb = h2f(saw[jj]);
                    float2 fc = h2f(rbw[jj]), fd = h2f(sbw[jj]);
                    c1[jj][0] = fa.x + fb.x;
                    c1[jj][1] = fa.y + fb.y;
                    c1[jj][2] = fc.x + fd.x;
                    c1[jj][3] = fc.y + fd.y;
                }
            }
#pragma unroll
            for (int jj = 0; jj < 4; jj++) {
                int J = 4 * jc + jj;
#pragma unroll
                for (int s = 0; s < 4; s++) {
                    uint2 f = w1h[(J * 4 + s) * 32 + lid];
                    mma_f16(c1[jj], a1[s], f.x, f.y);
                }
            }
            // relu + fp16 pack into A2 frags (t = 2jc, 2jc+1)
#pragma unroll
            for (int p = 0; p < 2; p++) {
                int t = 2 * jc + p;
                a2[t][0] = pack_h2(fmaxf(c1[2 * p][0], 0.0f),     fmaxf(c1[2 * p][1], 0.0f));
                a2[t][1] = pack_h2(fmaxf(c1[2 * p][2], 0.0f),     fmaxf(c1[2 * p][3], 0.0f));
                a2[t][2] = pack_h2(fmaxf(c1[2 * p + 1][0], 0.0f), fmaxf(c1[2 * p + 1][1], 0.0f));
                a2[t][3] = pack_h2(fmaxf(c1[2 * p + 1][2], 0.0f), fmaxf(c1[2 * p + 1][3], 0.0f));
            }
        }

        // ---- GEMM2 (single-term) in 2 halves of 4 j, stores interleaved
#pragma unroll
        for (int jh = 0; jh < 2; jh++) {
            float d2[4][4];
#pragma unroll
            for (int jj = 0; jj < 4; jj++) {
                int j = 4 * jh + jj;
                float2 bb = *(const float2*)(b2f + 8 * j + 2 * tg);
                d2[jj][0] = bb.x; d2[jj][1] = bb.y;
                d2[jj][2] = bb.x; d2[jj][3] = bb.y;
            }
#pragma unroll
            for (int jj = 0; jj < 4; jj++) {
                int j = 4 * jh + jj;
#pragma unroll
                for (int t = 0; t < 8; t++) {
                    uint2 f = w2h[(j * 8 + t) * 32 + lid];
                    mma_f16(d2[jj], a2[t], f.x, f.y);
                }
            }
            if (em0 < N_EDGES_C) {
                float* o0 = out + (size_t)em0 * 64 + 32 * jh;
#pragma unroll
                for (int jj = 0; jj < 4; jj++)
                    *(float2*)(o0 + 8 * jj + 2 * tg) = make_float2(d2[jj][0], d2[jj][1]);
            }
            if (em1 < N_EDGES_C) {
                float* o1 = out + (size_t)em1 * 64 + 32 * jh;
#pragma unroll
                for (int jj = 0; jj < 4; jj++)
                    *(float2*)(o1 + 8 * jj + 2 * tg) = make_float2(d2[jj][2], d2[jj][3]);
            }
        }
    }
}

// ---------------------------------------------------------------------------
extern "C" void kernel_launch(void* const* d_in, const int* in_sizes, int n_in,
                              void* d_out, int out_size) {
    const float* edata     = (const float*)d_in[0];
    const float* vfeat     = (const float*)d_in[1];
    const float* W1        = (const float*)d_in[2];
    const float* b1        = (const float*)d_in[3];
    const float* W2        = (const float*)d_in[4];
    const float* b2        = (const float*)d_in[5];
    const void*  senders   = d_in[6];
    const void*  receivers = d_in[7];
    float* out = (float*)d_out;
    (void)in_sizes; (void)n_in; (void)out_size;

    const int pc_smem = (64 * 256 + PC_TILE * 64) * 4;             // 81920 B
    const int e_smem  = 2048 * 8 * 2 + 64 * 4 + 16;                // 33040 B

    cudaFuncSetAttribute(precompute_kernel,
                         cudaFuncAttributeMaxDynamicSharedMemorySize, pc_smem);
    cudaFuncSetAttribute(edge_kernel,
                         cudaFuncAttributeMaxDynamicSharedMemorySize, e_smem);

    int sms = 0;
    cudaDeviceGetAttribute(&sms, cudaDevAttrMultiProcessorCount, 0);
    if (sms <= 0) sms = 148;

    precompute_kernel<<<(N_NODES + PC_TILE - 1) / PC_TILE, 256, pc_smem>>>(vfeat, W1, b1);
    edge_kernel<<<sms, NT, e_smem>>>(edata, W1, W2, b2, senders, receivers, out);
}

// round 12
// speedup vs baseline: 2.7687x; 1.0835x over previous
#include <cuda_runtime.h>
#include <cuda_fp16.h>
#include <cstdint>

#define N_NODES   50000
#define N_EDGES_C 1600000
#define TILE_E    320
#define NT        320
#define PC_NODES  128

// Scratch: per-node fp16 [vfeat@W1_recv + 0.5*b1 | vfeat@W1_send + 0.5*b1],
// chunk-major permuted: half index = jc*32 + tg*8 + jj*2 + c  where
// col = 8*(4*jc+jj) + 2*tg + c.  Each (row, jc) chunk is 64 B contiguous.
__device__ __half g_Ph[(size_t)N_NODES * 256];

// ============================ helpers ============================
__device__ __forceinline__ void mma_f16(float* c, const uint32_t* a, uint32_t b0, uint32_t b1) {
    asm volatile("mma.sync.aligned.m16n8k16.row.col.f32.f16.f16.f32 "
        "{%0,%1,%2,%3}, {%4,%5,%6,%7}, {%8,%9}, {%0,%1,%2,%3};"
        : "+f"(c[0]), "+f"(c[1]), "+f"(c[2]), "+f"(c[3])
        : "r"(a[0]), "r"(a[1]), "r"(a[2]), "r"(a[3]), "r"(b0), "r"(b1));
}

__device__ __forceinline__ uint32_t pack_h2(float x, float y) {
    __half2 h = __floats2half2_rn(x, y);
    return *reinterpret_cast<uint32_t*>(&h);
}
__device__ __forceinline__ void wsplit(float w0, float w1, uint32_t& hi, uint32_t& lo) {
    float h0 = __half2float(__float2half_rn(w0));
    float h1 = __half2float(__float2half_rn(w1));
    hi = pack_h2(h0, h1);
    lo = pack_h2(w0 - h0, w1 - h1);
}
__device__ __forceinline__ float2 h2f(uint32_t u) {
    __half2 h = *reinterpret_cast<__half2*>(&u);
    return __half22float2(h);
}

// ---------------------------------------------------------------------------
// HMMA precompute: P[n] = vfeat[n] @ W1cat + 0.5*b1  (both halves),
// 3-term fp16 (vh@Wh + vl@Wh + vh@Wl), stored fp16 chunk-major permuted with
// fully coalesced uint4 stores. W1cat[k][col] = col<128 ? W1[(64+k)][col]
//                                             : W1[(128+k)][col-128]
// 256 threads, 8 warps x 16 nodes = 128 nodes/CTA.
// ---------------------------------------------------------------------------
__global__ void __launch_bounds__(256)
precompute_kernel(const float* __restrict__ vfeat, const float* __restrict__ W1,
                  const float* __restrict__ b1) {
    extern __shared__ char smraw[];
    uint4* wc = (uint4*)smraw;   // [32 J][4 s][32 lane] {b0h,b1h,b0l,b1l}  64 KB

    const int tid = threadIdx.x;
    const int wid = tid >> 5, lid = tid & 31;
    const int gq  = lid >> 2;
    const int tg  = lid & 3;

    // Stage W1cat fragments (hi/lo interleaved)
    for (int idx = tid; idx < 4096; idx += 256) {
        int lane = idx & 31, s = (idx >> 5) & 3, J = idx >> 7;
        int k = 16 * s + 2 * (lane & 3);
        int col = 8 * J + (lane >> 2);
        int r0 = (col < 128) ? (64 + k)  : (128 + k);
        int c0 = (col < 128) ? col : (col - 128);
        uint4 f;
        wsplit(W1[r0 * 128 + c0],       W1[(r0 + 1) * 128 + c0], f.x, f.z);
        wsplit(W1[(r0 + 8) * 128 + c0], W1[(r0 + 9) * 128 + c0], f.y, f.w);
        wc[idx] = f;
    }
    __syncthreads();

    const int n0 = blockIdx.x * PC_NODES + wid * 16 + gq;
    const int n1 = n0 + 8;
    const int n0c = n0 < N_NODES ? n0 : (N_NODES - 1);
    const int n1c = n1 < N_NODES ? n1 : (N_NODES - 1);

    // A fragments from vfeat (fp16 hi/lo)
    uint32_t ah[4][4], al[4][4];
    {
        const float* v0 = vfeat + (size_t)n0c * 64;
        const float* v1 = vfeat + (size_t)n1c * 64;
#pragma unroll
        for (int s = 0; s < 4; s++) {
            int k = 16 * s + 2 * tg;
            float2 x0 = *(const float2*)(v0 + k);
            float2 x1 = *(const float2*)(v1 + k);
            float2 x2 = *(const float2*)(v0 + k + 8);
            float2 x3 = *(const float2*)(v1 + k + 8);
            wsplit(x0.x, x0.y, ah[s][0], al[s][0]);
            wsplit(x1.x, x1.y, ah[s][1], al[s][1]);
            wsplit(x2.x, x2.y, ah[s][2], al[s][2]);
            wsplit(x3.x, x3.y, ah[s][3], al[s][3]);
        }
    }

    // Accumulators init with 0.5*b1 (per output column), then 3-term mma
    float c[32][4];
#pragma unroll
    for (int J = 0; J < 32; J++) {
        int col = 8 * J + 2 * tg;
        float bb0 = 0.5f * b1[col & 127];
        float bb1 = 0.5f * b1[(col + 1) & 127];
        c[J][0] = bb0; c[J][1] = bb1; c[J][2] = bb0; c[J][3] = bb1;
    }
#pragma unroll
    for (int J = 0; J < 32; J++) {
#pragma unroll
        for (int s = 0; s < 4; s++) {
            uint4 f = wc[(J * 4 + s) * 32 + lid];
            mma_f16(c[J], ah[s], f.x, f.y);
            mma_f16(c[J], al[s], f.x, f.y);
            mma_f16(c[J], ah[s], f.z, f.w);
        }
    }

    // Coalesced permuted stores: per (node, h, jc) a lane-quad writes 64 B.
    char* Pb = (char*)g_Ph;
#pragma unroll
    for (int h = 0; h < 2; h++) {
#pragma unroll
        for (int jc = 0; jc < 4; jc++) {
            uint4 u0, u1;
            uint32_t* p0 = (uint32_t*)&u0;
            uint32_t* p1 = (uint32_t*)&u1;
#pragma unroll
            for (int jj = 0; jj < 4; jj++) {
                int J = h * 16 + 4 * jc + jj;
                p0[jj] = pack_h2(c[J][0], c[J][1]);
                p1[jj] = pack_h2(c[J][2], c[J][3]);
            }
            uint32_t off = (uint32_t)h * 256u + jc * 64u + tg * 16u;
            if (n0 < N_NODES) *(uint4*)(Pb + (size_t)n0 * 512 + off) = u0;
            if (n1 < N_NODES) *(uint4*)(Pb + (size_t)n1 * 512 + off) = u1;
        }
    }
}

// ---------------------------------------------------------------------------
// Persistent HMMA edge kernel. fp16 single-term weights, fp16 activations.
// 320 threads (10 warps)/CTA, M=32 rows/warp, TILE_E=320.
// ---------------------------------------------------------------------------
__global__ void __launch_bounds__(NT, 1)
edge_kernel(const float* __restrict__ edata,
            const float* __restrict__ W1,
            const float* __restrict__ W2,
            const float* __restrict__ b2,
            const void*  __restrict__ senders,
            const void*  __restrict__ receivers,
            float* __restrict__ out) {
    extern __shared__ char smraw[];
    uint2* w1h = (uint2*)smraw;              // [16 J][4 s][32 lane] hi   16 KB
    uint2* w2h = (uint2*)(w1h + 2048);       // [8 j][8 t][32 lane] hi    16 KB
    float* b2f = (float*)(w2h + 2048);       // 64
    int*   sFlag = (int*)(b2f + 64);

    const int tid = threadIdx.x;
    const int wid = tid >> 5, lid = tid & 31;
    const int gq  = lid >> 2;     // fragment row
    const int tg  = lid & 3;      // fragment col pair

    if (tid < 32) {
        unsigned hiw = ((const unsigned*)senders)[2 * tid + 1];
        unsigned ball = __ballot_sync(0xffffffffu, hiw == 0u);
        if (tid == 0) *sFlag = (ball == 0xffffffffu);
    }

    // ---- Stage W1 fragments (fp16 hi only)
    for (int idx = tid; idx < 2048; idx += NT) {
        int lane = idx & 31, s = (idx >> 5) & 3, j = idx >> 7;
        int k = 16 * s + 2 * (lane & 3);
        int n = 8 * j + (lane >> 2);
        uint2 f;
        f.x = pack_h2(W1[k * 128 + n],       W1[(k + 1) * 128 + n]);
        f.y = pack_h2(W1[(k + 8) * 128 + n], W1[(k + 9) * 128 + n]);
        w1h[idx] = f;
    }
    // ---- Stage W2 fragments (fp16 hi only)
    for (int idx = tid; idx < 2048; idx += NT) {
        int lane = idx & 31, t = (idx >> 5) & 7, j = idx >> 8;
        int k = 16 * t + 2 * (lane & 3);
        int n = 8 * j + (lane >> 2);
        uint2 f;
        f.x = pack_h2(W2[k * 64 + n],       W2[(k + 1) * 64 + n]);
        f.y = pack_h2(W2[(k + 8) * 64 + n], W2[(k + 9) * 64 + n]);
        w2h[idx] = f;
    }
    if (tid < 64) b2f[tid] = b2[tid];
    __syncthreads();

    const int idx64 = *sFlag;
    const long long* r64 = (const long long*)receivers;
    const int*       r32 = (const int*)receivers;
    const long long* s64 = (const long long*)senders;
    const int*       s32 = (const int*)senders;

    const char* Pbase = (const char*)g_Ph;
    const int ntiles = (N_EDGES_C + TILE_E - 1) / TILE_E;   // 5000 exact

    for (int tile = blockIdx.x; tile < ntiles; tile += gridDim.x) {
        const int base = tile * TILE_E + wid * 32 + gq;
        int em[4];
        em[0] = base;      em[1] = base + 8;
        em[2] = base + 16; em[3] = base + 24;

        uint32_t offR[4], offS[4];
#pragma unroll
        for (int q = 0; q < 4; q++) {
            int e = em[q] < N_EDGES_C ? em[q] : (N_EDGES_C - 1);
            int rr = idx64 ? (int)r64[e] : r32[e];
            int ss = idx64 ? (int)s64[e] : s32[e];
            offR[q] = (uint32_t)rr * 512u + tg * 16u;
            offS[q] = (uint32_t)ss * 512u + 256u + tg * 16u;
        }

        // ---- A1 fragments from edata (fp16 quantize)
        uint32_t a1[2][4][4];
#pragma unroll
        for (int b = 0; b < 2; b++) {
            int e0 = em[2 * b] < N_EDGES_C ? em[2 * b] : (N_EDGES_C - 1);
            int e1 = em[2 * b + 1] < N_EDGES_C ? em[2 * b + 1] : (N_EDGES_C - 1);
            const float* x0 = edata + (size_t)e0 * 64;
            const float* x1 = edata + (size_t)e1 * 64;
#pragma unroll
            for (int s = 0; s < 4; s++) {
                int k = 16 * s + 2 * tg;
                float2 v0 = *(const float2*)(x0 + k);
                float2 v1 = *(const float2*)(x1 + k);
                float2 v2 = *(const float2*)(x0 + k + 8);
                float2 v3 = *(const float2*)(x1 + k + 8);
                a1[b][s][0] = pack_h2(v0.x, v0.y);
                a1[b][s][1] = pack_h2(v1.x, v1.y);
                a1[b][s][2] = pack_h2(v2.x, v2.y);
                a1[b][s][3] = pack_h2(v3.x, v3.y);
            }
        }

        // ---- GEMM1 in 4 chunks of 4 J; produce fp16 A2 fragments
        uint32_t a2[2][8][4];
#pragma unroll
        for (int jc = 0; jc < 4; jc++) {
            float c1[2][4][4];
#pragma unroll
            for (int b = 0; b < 2; b++) {
                uint4 ra = *(const uint4*)(Pbase + offR[2 * b]     + jc * 64);
                uint4 sa = *(const uint4*)(Pbase + offS[2 * b]     + jc * 64);
                uint4 rb = *(const uint4*)(Pbase + offR[2 * b + 1] + jc * 64);
                uint4 sb = *(const uint4*)(Pbase + offS[2 * b + 1] + jc * 64);
                const uint32_t* raw = (const uint32_t*)&ra;
                const uint32_t* saw = (const uint32_t*)&sa;
                const uint32_t* rbw = (const uint32_t*)&rb;
                const uint32_t* sbw = (const uint32_t*)&sb;
#pragma unroll
                for (int jj = 0; jj < 4; jj++) {
                    float2 fa = h2f(raw[jj]), fb = h2f(saw[jj]);
                    float2 fc = h2f(rbw[jj]), fd = h2f(sbw[jj]);
                    c1[b][jj][0] = fa.x + fb.x;
                    c1[b][jj][1] = fa.y + fb.y;
                    c1[b][jj][2] = fc.x + fd.x;
                    c1[b][jj][3] = fc.y + fd.y;
                }
            }
#pragma unroll
            for (int jj = 0; jj < 4; jj++) {
                int J = 4 * jc + jj;
#pragma unroll
                for (int s = 0; s < 4; s++) {
                    uint2 f = w1h[(J * 4 + s) * 32 + lid];
#pragma unroll
                    for (int b = 0; b < 2; b++)
                        mma_f16(c1[b][jj], a1[b][s], f.x, f.y);
                }
            }
            // relu + fp16 pack into A2 frags (t = 2jc, 2jc+1)
#pragma unroll
            for (int b = 0; b < 2; b++) {
#pragma unroll
                for (int p = 0; p < 2; p++) {
                    int t = 2 * jc + p;
                    a2[b][t][0] = pack_h2(fmaxf(c1[b][2 * p][0], 0.0f),     fmaxf(c1[b][2 * p][1], 0.0f));
                    a2[b][t][1] = pack_h2(fmaxf(c1[b][2 * p][2], 0.0f),     fmaxf(c1[b][2 * p][3], 0.0f));
                    a2[b][t][2] = pack_h2(fmaxf(c1[b][2 * p + 1][0], 0.0f), fmaxf(c1[b][2 * p + 1][1], 0.0f));
                    a2[b][t][3] = pack_h2(fmaxf(c1[b][2 * p + 1][2], 0.0f), fmaxf(c1[b][2 * p + 1][3], 0.0f));
                }
            }
        }

        // ---- GEMM2 (single-term) in 2 halves of 4 j, stores interleaved
#pragma unroll
        for (int jh = 0; jh < 2; jh++) {
            float d2[2][4][4];
#pragma unroll
            for (int jj = 0; jj < 4; jj++) {
                int j = 4 * jh + jj;
                float2 bb = *(const float2*)(b2f + 8 * j + 2 * tg);
#pragma unroll
                for (int b = 0; b < 2; b++) {
                    d2[b][jj][0] = bb.x; d2[b][jj][1] = bb.y;
                    d2[b][jj][2] = bb.x; d2[b][jj][3] = bb.y;
                }
            }
#pragma unroll
            for (int jj = 0; jj < 4; jj++) {
                int j = 4 * jh + jj;
#pragma unroll
                for (int t = 0; t < 8; t++) {
                    uint2 f = w2h[(j * 8 + t) * 32 + lid];
#pragma unroll
                    for (int b = 0; b < 2; b++)
                        mma_f16(d2[b][jj], a2[b][t], f.x, f.y);
                }
            }
#pragma unroll
            for (int b = 0; b < 2; b++) {
                if (em[2 * b] < N_EDGES_C) {
                    float* o0 = out + (size_t)em[2 * b] * 64 + 32 * jh;
#pragma unroll
                    for (int jj = 0; jj < 4; jj++)
                        *(float2*)(o0 + 8 * jj + 2 * tg) = make_float2(d2[b][jj][0], d2[b][jj][1]);
                }
                if (em[2 * b + 1] < N_EDGES_C) {
                    float* o1 = out + (size_t)em[2 * b + 1] * 64 + 32 * jh;
#pragma unroll
                    for (int jj = 0; jj < 4; jj++)
                        *(float2*)(o1 + 8 * jj + 2 * tg) = make_float2(d2[b][jj][2], d2[b][jj][3]);
                }
            }
        }
    }
}

// ---------------------------------------------------------------------------
extern "C" void kernel_launch(void* const* d_in, const int* in_sizes, int n_in,
                              void* d_out, int out_size) {
    const float* edata     = (const float*)d_in[0];
    const float* vfeat     = (const float*)d_in[1];
    const float* W1        = (const float*)d_in[2];
    const float* b1        = (const float*)d_in[3];
    const float* W2        = (const float*)d_in[4];
    const float* b2        = (const float*)d_in[5];
    const void*  senders   = d_in[6];
    const void*  receivers = d_in[7];
    float* out = (float*)d_out;
    (void)in_sizes; (void)n_in; (void)out_size;

    const int pc_smem = 4096 * 16;                                  // 65536 B
    const int e_smem  = 2048 * 8 * 2 + 64 * 4 + 16;                 // 33040 B

    cudaFuncSetAttribute(precompute_kernel,
                         cudaFuncAttributeMaxDynamicSharedMemorySize, pc_smem);
    cudaFuncSetAttribute(edge_kernel,
                         cudaFuncAttributeMaxDynamicSharedMemorySize, e_smem);

    int sms = 0;
    cudaDeviceGetAttribute(&sms, cudaDevAttrMultiProcessorCount, 0);
    if (sms <= 0) sms = 148;

    precompute_kernel<<<(N_NODES + PC_NODES - 1) / PC_NODES, 256, pc_smem>>>(vfeat, W1, b1);
    edge_kernel<<<sms, NT, e_smem>>>(edata, W1, W2, b2, senders, receivers, out);
}

// round 13
// speedup vs baseline: 2.9718x; 1.0733x over previous
#include <cuda_runtime.h>
#include <cuda_fp16.h>
#include <cstdint>

#define N_NODES   50000
#define N_EDGES_C 1600000
#define TILE_E    256
#define NT        512
#define PC_NODES  128

// Scratch: per-node fp16 [vfeat@W1_recv + 0.5*b1 | vfeat@W1_send + 0.5*b1],
// chunk-major permuted: half index = jc*32 + tg*8 + jj*2 + c  where
// col = 8*(4*jc+jj) + 2*tg + c.  Each (row, jc) chunk is 64 B contiguous.
__device__ __half g_Ph[(size_t)N_NODES * 256];

// ============================ helpers ============================
__device__ __forceinline__ void mma_f16(float* c, const uint32_t* a, uint32_t b0, uint32_t b1) {
    asm volatile("mma.sync.aligned.m16n8k16.row.col.f32.f16.f16.f32 "
        "{%0,%1,%2,%3}, {%4,%5,%6,%7}, {%8,%9}, {%0,%1,%2,%3};"
        : "+f"(c[0]), "+f"(c[1]), "+f"(c[2]), "+f"(c[3])
        : "r"(a[0]), "r"(a[1]), "r"(a[2]), "r"(a[3]), "r"(b0), "r"(b1));
}

__device__ __forceinline__ uint32_t pack_h2(float x, float y) {
    __half2 h = __floats2half2_rn(x, y);
    return *reinterpret_cast<uint32_t*>(&h);
}
__device__ __forceinline__ void wsplit(float w0, float w1, uint32_t& hi, uint32_t& lo) {
    float h0 = __half2float(__float2half_rn(w0));
    float h1 = __half2float(__float2half_rn(w1));
    hi = pack_h2(h0, h1);
    lo = pack_h2(w0 - h0, w1 - h1);
}
__device__ __forceinline__ float2 h2f(uint32_t u) {
    __half2 h = *reinterpret_cast<__half2*>(&u);
    return __half22float2(h);
}

// ---------------------------------------------------------------------------
// HMMA precompute: P[n] = vfeat[n] @ W1cat + 0.5*b1  (both halves),
// 3-term fp16 (vh@Wh + vl@Wh + vh@Wl), stored fp16 chunk-major permuted with
// fully coalesced uint4 stores. 256 threads, 8 warps x 16 nodes = 128 nodes/CTA.
// ---------------------------------------------------------------------------
__global__ void __launch_bounds__(256)
precompute_kernel(const float* __restrict__ vfeat, const float* __restrict__ W1,
                  const float* __restrict__ b1) {
    extern __shared__ char smraw[];
    uint4* wc = (uint4*)smraw;   // [32 J][4 s][32 lane] {b0h,b1h,b0l,b1l}  64 KB

    const int tid = threadIdx.x;
    const int wid = tid >> 5, lid = tid & 31;
    const int gq  = lid >> 2;
    const int tg  = lid & 3;

    // Stage W1cat fragments (hi/lo interleaved)
    for (int idx = tid; idx < 4096; idx += 256) {
        int lane = idx & 31, s = (idx >> 5) & 3, J = idx >> 7;
        int k = 16 * s + 2 * (lane & 3);
        int col = 8 * J + (lane >> 2);
        int r0 = (col < 128) ? (64 + k)  : (128 + k);
        int c0 = (col < 128) ? col : (col - 128);
        uint4 f;
        wsplit(W1[r0 * 128 + c0],       W1[(r0 + 1) * 128 + c0], f.x, f.z);
        wsplit(W1[(r0 + 8) * 128 + c0], W1[(r0 + 9) * 128 + c0], f.y, f.w);
        wc[idx] = f;
    }
    __syncthreads();

    const int n0 = blockIdx.x * PC_NODES + wid * 16 + gq;
    const int n1 = n0 + 8;
    const int n0c = n0 < N_NODES ? n0 : (N_NODES - 1);
    const int n1c = n1 < N_NODES ? n1 : (N_NODES - 1);

    // A fragments from vfeat (fp16 hi/lo)
    uint32_t ah[4][4], al[4][4];
    {
        const float* v0 = vfeat + (size_t)n0c * 64;
        const float* v1 = vfeat + (size_t)n1c * 64;
#pragma unroll
        for (int s = 0; s < 4; s++) {
            int k = 16 * s + 2 * tg;
            float2 x0 = *(const float2*)(v0 + k);
            float2 x1 = *(const float2*)(v1 + k);
            float2 x2 = *(const float2*)(v0 + k + 8);
            float2 x3 = *(const float2*)(v1 + k + 8);
            wsplit(x0.x, x0.y, ah[s][0], al[s][0]);
            wsplit(x1.x, x1.y, ah[s][1], al[s][1]);
            wsplit(x2.x, x2.y, ah[s][2], al[s][2]);
            wsplit(x3.x, x3.y, ah[s][3], al[s][3]);
        }
    }

    // Accumulators init with 0.5*b1, then 3-term mma
    float c[32][4];
#pragma unroll
    for (int J = 0; J < 32; J++) {
        int col = 8 * J + 2 * tg;
        float bb0 = 0.5f * b1[col & 127];
        float bb1 = 0.5f * b1[(col + 1) & 127];
        c[J][0] = bb0; c[J][1] = bb1; c[J][2] = bb0; c[J][3] = bb1;
    }
#pragma unroll
    for (int J = 0; J < 32; J++) {
#pragma unroll
        for (int s = 0; s < 4; s++) {
            uint4 f = wc[(J * 4 + s) * 32 + lid];
            mma_f16(c[J], ah[s], f.x, f.y);
            mma_f16(c[J], al[s], f.x, f.y);
            mma_f16(c[J], ah[s], f.z, f.w);
        }
    }

    // Coalesced permuted stores: per (node, h, jc) a lane-quad writes 64 B.
    char* Pb = (char*)g_Ph;
#pragma unroll
    for (int h = 0; h < 2; h++) {
#pragma unroll
        for (int jc = 0; jc < 4; jc++) {
            uint4 u0, u1;
            uint32_t* p0 = (uint32_t*)&u0;
            uint32_t* p1 = (uint32_t*)&u1;
#pragma unroll
            for (int jj = 0; jj < 4; jj++) {
                int J = h * 16 + 4 * jc + jj;
                p0[jj] = pack_h2(c[J][0], c[J][1]);
                p1[jj] = pack_h2(c[J][2], c[J][3]);
            }
            uint32_t off = (uint32_t)h * 256u + jc * 64u + tg * 16u;
            if (n0 < N_NODES) *(uint4*)(Pb + (size_t)n0 * 512 + off) = u0;
            if (n1 < N_NODES) *(uint4*)(Pb + (size_t)n1 * 512 + off) = u1;
        }
    }
}

// ---------------------------------------------------------------------------
// Persistent HMMA edge kernel. fp16 single-term weights, fp16 activations.
// 512 threads (16 warps)/CTA, M=16 rows/warp, TILE_E=256/CTA-iter.
// Low register footprint (~124) -> 16 warps/SM for latency hiding.
// ---------------------------------------------------------------------------
__global__ void __launch_bounds__(NT, 1)
edge_kernel(const float* __restrict__ edata,
            const float* __restrict__ W1,
            const float* __restrict__ W2,
            const float* __restrict__ b2,
            const void*  __restrict__ senders,
            const void*  __restrict__ receivers,
            float* __restrict__ out) {
    extern __shared__ char smraw[];
    uint2* w1h = (uint2*)smraw;              // [16 J][4 s][32 lane] hi   16 KB
    uint2* w2h = (uint2*)(w1h + 2048);       // [8 j][8 t][32 lane] hi    16 KB
    float* b2f = (float*)(w2h + 2048);       // 64
    int*   sFlag = (int*)(b2f + 64);

    const int tid = threadIdx.x;
    const int wid = tid >> 5, lid = tid & 31;
    const int gq  = lid >> 2;     // fragment row
    const int tg  = lid & 3;      // fragment col pair

    if (tid < 32) {
        unsigned hiw = ((const unsigned*)senders)[2 * tid + 1];
        unsigned ball = __ballot_sync(0xffffffffu, hiw == 0u);
        if (tid == 0) *sFlag = (ball == 0xffffffffu);
    }

    // ---- Stage W1 fragments (fp16 hi only)
    for (int idx = tid; idx < 2048; idx += NT) {
        int lane = idx & 31, s = (idx >> 5) & 3, j = idx >> 7;
        int k = 16 * s + 2 * (lane & 3);
        int n = 8 * j + (lane >> 2);
        uint2 f;
        f.x = pack_h2(W1[k * 128 + n],       W1[(k + 1) * 128 + n]);
        f.y = pack_h2(W1[(k + 8) * 128 + n], W1[(k + 9) * 128 + n]);
        w1h[idx] = f;
    }
    // ---- Stage W2 fragments (fp16 hi only)
    for (int idx = tid; idx < 2048; idx += NT) {
        int lane = idx & 31, t = (idx >> 5) & 7, j = idx >> 8;
        int k = 16 * t + 2 * (lane & 3);
        int n = 8 * j + (lane >> 2);
        uint2 f;
        f.x = pack_h2(W2[k * 64 + n],       W2[(k + 1) * 64 + n]);
        f.y = pack_h2(W2[(k + 8) * 64 + n], W2[(k + 9) * 64 + n]);
        w2h[idx] = f;
    }
    if (tid < 64) b2f[tid] = b2[tid];
    __syncthreads();

    const int idx64 = *sFlag;
    const long long* r64 = (const long long*)receivers;
    const int*       r32 = (const int*)receivers;
    const long long* s64 = (const long long*)senders;
    const int*       s32 = (const int*)senders;

    const char* Pbase = (const char*)g_Ph;
    const int ntiles = (N_EDGES_C + TILE_E - 1) / TILE_E;   // 6250 exact

    for (int tile = blockIdx.x; tile < ntiles; tile += gridDim.x) {
        const int base = tile * TILE_E + wid * 16 + gq;
        const int em0 = base, em1 = base + 8;
        const int e0c = em0 < N_EDGES_C ? em0 : (N_EDGES_C - 1);
        const int e1c = em1 < N_EDGES_C ? em1 : (N_EDGES_C - 1);

        uint32_t offR0, offS0, offR1, offS1;
        {
            int rr0 = idx64 ? (int)r64[e0c] : r32[e0c];
            int ss0 = idx64 ? (int)s64[e0c] : s32[e0c];
            int rr1 = idx64 ? (int)r64[e1c] : r32[e1c];
            int ss1 = idx64 ? (int)s64[e1c] : s32[e1c];
            offR0 = (uint32_t)rr0 * 512u + tg * 16u;
            offS0 = (uint32_t)ss0 * 512u + 256u + tg * 16u;
            offR1 = (uint32_t)rr1 * 512u + tg * 16u;
            offS1 = (uint32_t)ss1 * 512u + 256u + tg * 16u;
        }

        // ---- A1 fragments from edata (fp16 quantize)
        uint32_t a1[4][4];
        {
            const float* x0 = edata + (size_t)e0c * 64;
            const float* x1 = edata + (size_t)e1c * 64;
#pragma unroll
            for (int s = 0; s < 4; s++) {
                int k = 16 * s + 2 * tg;
                float2 v0 = *(const float2*)(x0 + k);
                float2 v1 = *(const float2*)(x1 + k);
                float2 v2 = *(const float2*)(x0 + k + 8);
                float2 v3 = *(const float2*)(x1 + k + 8);
                a1[s][0] = pack_h2(v0.x, v0.y);
                a1[s][1] = pack_h2(v1.x, v1.y);
                a1[s][2] = pack_h2(v2.x, v2.y);
                a1[s][3] = pack_h2(v3.x, v3.y);
            }
        }

        // ---- GEMM1 in 4 chunks of 4 J; produce fp16 A2 fragments
        uint32_t a2[8][4];
#pragma unroll
        for (int jc = 0; jc < 4; jc++) {
            float c1[4][4];
            {
                uint4 ra = *(const uint4*)(Pbase + offR0 + jc * 64);
                uint4 sa = *(const uint4*)(Pbase + offS0 + jc * 64);
                uint4 rb = *(const uint4*)(Pbase + offR1 + jc * 64);
                uint4 sb = *(const uint4*)(Pbase + offS1 + jc * 64);
                const uint32_t* raw = (const uint32_t*)&ra;
                const uint32_t* saw = (const uint32_t*)&sa;
                const uint32_t* rbw = (const uint32_t*)&rb;
                const uint32_t* sbw = (const uint32_t*)&sb;
#pragma unroll
                for (int jj = 0; jj < 4; jj++) {
                    float2 fa = h2f(raw[jj]), fb = h2f(saw[jj]);
                    float2 fc = h2f(rbw[jj]), fd = h2f(sbw[jj]);
                    c1[jj][0] = fa.x + fb.x;
                    c1[jj][1] = fa.y + fb.y;
                    c1[jj][2] = fc.x + fd.x;
                    c1[jj][3] = fc.y + fd.y;
                }
            }
#pragma unroll
            for (int jj = 0; jj < 4; jj++) {
                int J = 4 * jc + jj;
#pragma unroll
                for (int s = 0; s < 4; s++) {
                    uint2 f = w1h[(J * 4 + s) * 32 + lid];
                    mma_f16(c1[jj], a1[s], f.x, f.y);
                }
            }
            // relu + fp16 pack into A2 frags (t = 2jc, 2jc+1)
#pragma unroll
            for (int p = 0; p < 2; p++) {
                int t = 2 * jc + p;
                a2[t][0] = pack_h2(fmaxf(c1[2 * p][0], 0.0f),     fmaxf(c1[2 * p][1], 0.0f));
                a2[t][1] = pack_h2(fmaxf(c1[2 * p][2], 0.0f),     fmaxf(c1[2 * p][3], 0.0f));
                a2[t][2] = pack_h2(fmaxf(c1[2 * p + 1][0], 0.0f), fmaxf(c1[2 * p + 1][1], 0.0f));
                a2[t][3] = pack_h2(fmaxf(c1[2 * p + 1][2], 0.0f), fmaxf(c1[2 * p + 1][3], 0.0f));
            }
        }

        // ---- GEMM2 (single-term) in 2 halves of 4 j, stores interleaved
#pragma unroll
        for (int jh = 0; jh < 2; jh++) {
            float d2[4][4];
#pragma unroll
            for (int jj = 0; jj < 4; jj++) {
                int j = 4 * jh + jj;
                float2 bb = *(const float2*)(b2f + 8 * j + 2 * tg);
                d2[jj][0] = bb.x; d2[jj][1] = bb.y;
                d2[jj][2] = bb.x; d2[jj][3] = bb.y;
            }
#pragma unroll
            for (int jj = 0; jj < 4; jj++) {
                int j = 4 * jh + jj;
#pragma unroll
                for (int t = 0; t < 8; t++) {
                    uint2 f = w2h[(j * 8 + t) * 32 + lid];
                    mma_f16(d2[jj], a2[t], f.x, f.y);
                }
            }
            if (em0 < N_EDGES_C) {
                float* o0 = out + (size_t)em0 * 64 + 32 * jh;
#pragma unroll
                for (int jj = 0; jj < 4; jj++)
                    *(float2*)(o0 + 8 * jj + 2 * tg) = make_float2(d2[jj][0], d2[jj][1]);
            }
            if (em1 < N_EDGES_C) {
                float* o1 = out + (size_t)em1 * 64 + 32 * jh;
#pragma unroll
                for (int jj = 0; jj < 4; jj++)
                    *(float2*)(o1 + 8 * jj + 2 * tg) = make_float2(d2[jj][2], d2[jj][3]);
            }
        }
    }
}

// ---------------------------------------------------------------------------
extern "C" void kernel_launch(void* const* d_in, const int* in_sizes, int n_in,
                              void* d_out, int out_size) {
    const float* edata     = (const float*)d_in[0];
    const float* vfeat     = (const float*)d_in[1];
    const float* W1        = (const float*)d_in[2];
    const float* b1        = (const float*)d_in[3];
    const float* W2        = (const float*)d_in[4];
    const float* b2        = (const float*)d_in[5];
    const void*  senders   = d_in[6];
    const void*  receivers = d_in[7];
    float* out = (float*)d_out;
    (void)in_sizes; (void)n_in; (void)out_size;

    const int pc_smem = 4096 * 16;                                  // 65536 B
    const int e_smem  = 2048 * 8 * 2 + 64 * 4 + 16;                 // 33040 B

    cudaFuncSetAttribute(precompute_kernel,
                         cudaFuncAttributeMaxDynamicSharedMemorySize, pc_smem);
    cudaFuncSetAttribute(edge_kernel,
                         cudaFuncAttributeMaxDynamicSharedMemorySize, e_smem);

    int sms = 0;
    cudaDeviceGetAttribute(&sms, cudaDevAttrMultiProcessorCount, 0);
    if (sms <= 0) sms = 148;

    precompute_kernel<<<(N_NODES + PC_NODES - 1) / PC_NODES, 256, pc_smem>>>(vfeat, W1, b1);
    edge_kernel<<<sms, NT, e_smem>>>(edata, W1, W2, b2, senders, receivers, out);
}